// round 4
// baseline (speedup 1.0000x reference)
#include <cuda_runtime.h>
#include <math.h>

// Problem dims
#define LSEQ 512
#define NB   64      // batch
#define IDIM 1024
#define HDIM 1024
#define KTOT (IDIM + HDIM)   // 2048 (concat [x_t | h])

// Tiling
#define HC    8     // hidden cols per block
#define ZCOLS 32    // z-cols per block = 4 gates * HC
#define KB    64    // K chunk (never straddles the x|h boundary since IDIM%64==0)

#define AS_LD 68    // As row stride (17*16B -> LDS.128 aligned, conflict-free)
#define WS_LD 36    // Ws row stride (9*16B  -> LDS.128 aligned, conflict-free)

// Ping-pong recurrent state (device scratch; no allocation)
__device__ float g_h[2][NB * HDIM];
__device__ float g_c[2][NB * HDIM];

__global__ __launch_bounds__(128) void lstm_step(
    const float* __restrict__ xt,      // [NB, IDIM] slice for this t
    const float* __restrict__ h_ext,   // non-null only at t==0
    const float* __restrict__ c_ext,
    const float* __restrict__ Wih,     // [4H, I]
    const float* __restrict__ Whh,     // [4H, H]
    const float* __restrict__ bih,
    const float* __restrict__ bhh,
    int rd, int wr)
{
    __shared__ float As[KB][AS_LD];       // A chunk, transposed [k][row]
    __shared__ float Ws[KB][WS_LD];       // W chunk, transposed [k][zcol]
    __shared__ float Zs[NB][ZCOLS + 1];   // staged z tile

    const float* hp = h_ext ? h_ext : g_h[rd];
    const float* cp = c_ext ? c_ext : g_c[rd];
    float* hn = g_h[wr];
    float* cn = g_c[wr];

    const int tid = threadIdx.x;       // 128 threads
    const int tx  = tid & 7;           // col group: cols tx*4 .. tx*4+3  (of 32)
    const int ty  = tid >> 3;          // row group: rows ty*4 .. ty*4+3  (of 64)
    const int jh0 = blockIdx.x * HC;   // 128 blocks

    float acc[4][4] = {};

    for (int k0 = 0; k0 < KTOT; k0 += KB) {
        const float* Asrc = (k0 < IDIM) ? (xt + k0) : (hp + (k0 - IDIM));
        const float* Wsrc = (k0 < IDIM) ? (Wih + k0) : (Whh + (k0 - IDIM));

        // Load A chunk: 64 rows x 64 k = 1024 float4; 8 per thread.
        // r warp-distinct (0..31 within a warp) -> STS banks conflict-free.
        #pragma unroll
        for (int i = 0; i < 8; i++) {
            int idx = tid + i * 128;
            int r   = idx & 63;
            int q   = idx >> 6;        // float4 index within the 64-float chunk
            float4 v = *reinterpret_cast<const float4*>(Asrc + r * 1024 + 4 * q);
            As[4 * q + 0][r] = v.x;
            As[4 * q + 1][r] = v.y;
            As[4 * q + 2][r] = v.z;
            As[4 * q + 3][r] = v.w;
        }
        // Load W chunk: 32 zcols x 64 k = 512 float4; 4 per thread.
        // c warp-distinct (0..31) -> STS banks conflict-free.
        #pragma unroll
        for (int i = 0; i < 4; i++) {
            int idx = tid + i * 128;
            int c   = idx & 31;
            int q   = idx >> 5;
            int zc  = ((c >> 3) << 10) + jh0 + (c & 7);  // gate*1024 + hidden col
            float4 v = *reinterpret_cast<const float4*>(Wsrc + zc * 1024 + 4 * q);
            Ws[4 * q + 0][c] = v.x;
            Ws[4 * q + 1][c] = v.y;
            Ws[4 * q + 2][c] = v.z;
            Ws[4 * q + 3][c] = v.w;
        }
        __syncthreads();

        #pragma unroll 16
        for (int kk = 0; kk < KB; kk++) {
            float4 a = *reinterpret_cast<const float4*>(&As[kk][ty * 4]);
            float4 w = *reinterpret_cast<const float4*>(&Ws[kk][tx * 4]);
            acc[0][0] += a.x * w.x; acc[0][1] += a.x * w.y; acc[0][2] += a.x * w.z; acc[0][3] += a.x * w.w;
            acc[1][0] += a.y * w.x; acc[1][1] += a.y * w.y; acc[1][2] += a.y * w.z; acc[1][3] += a.y * w.w;
            acc[2][0] += a.z * w.x; acc[2][1] += a.z * w.y; acc[2][2] += a.z * w.z; acc[2][3] += a.z * w.w;
            acc[3][0] += a.w * w.x; acc[3][1] += a.w * w.y; acc[3][2] += a.w * w.z; acc[3][3] += a.w * w.w;
        }
        __syncthreads();
    }

    // Stage z tile with fused bias
    #pragma unroll
    for (int j = 0; j < 4; j++) {
        int c  = tx * 4 + j;
        int zc = ((c >> 3) << 10) + jh0 + (c & 7);
        float b = bih[zc] + bhh[zc];
        #pragma unroll
        for (int i = 0; i < 4; i++)
            Zs[ty * 4 + i][c] = acc[i][j] + b;
    }
    __syncthreads();

    // Gates: 64 rows x 8 hidden cols = 512 states, 4 per thread
    #pragma unroll
    for (int it = 0; it < 4; it++) {
        int idx = tid + it * 128;
        int r   = idx >> 3;
        int jj  = idx & 7;
        float zi = Zs[r][jj];
        float zf = Zs[r][8 + jj];
        float zg = Zs[r][16 + jj];
        float zo = Zs[r][24 + jj];
        int col = jh0 + jj;
        float cprev = cp[r * HDIM + col];
        float ig = 1.0f / (1.0f + expf(-zi));
        float fg = 1.0f / (1.0f + expf(-zf));
        float og = 1.0f / (1.0f + expf(-zo));
        float gg = tanhf(zg);
        float cnew = fg * cprev + ig * gg;
        cn[r * HDIM + col] = cnew;
        hn[r * HDIM + col] = og * tanhf(cnew);
    }
}

// y = h @ W_out^T + b_out   (one row n per blockIdx.y, 128 out cols per blockIdx.x)
__global__ __launch_bounds__(128) void out_proj(
    const float* __restrict__ Wout,   // [I, H]
    const float* __restrict__ bout,   // [I]
    float* __restrict__ y,            // out[0 : NB*IDIM]
    int hbuf)
{
    const float* h = g_h[hbuf];
    int n = blockIdx.y;
    int i = blockIdx.x * 128 + threadIdx.x;
    __shared__ float hs[HDIM];
    for (int k = threadIdx.x; k < HDIM; k += 128)
        hs[k] = h[n * HDIM + k];
    __syncthreads();
    float acc = bout[i];
    const float* wr = Wout + (size_t)i * HDIM;
    #pragma unroll 8
    for (int k = 0; k < HDIM; k++)
        acc += hs[k] * wr[k];
    y[n * IDIM + i] = acc;
}

__global__ void copy_hc(float* __restrict__ out, int buf)
{
    int idx = blockIdx.x * 256 + threadIdx.x;  // 65536 elements
    out[NB * IDIM + idx]               = g_h[buf][idx];
    out[NB * IDIM + NB * HDIM + idx]   = g_c[buf][idx];
}

extern "C" void kernel_launch(void* const* d_in, const int* in_sizes, int n_in,
                              void* d_out, int out_size)
{
    const float* x    = (const float*)d_in[0];  // [L, N, I]
    const float* h0   = (const float*)d_in[1];  // [N, H]
    const float* c0   = (const float*)d_in[2];  // [N, H]
    const float* Wih  = (const float*)d_in[3];  // [4H, I]
    const float* Whh  = (const float*)d_in[4];  // [4H, H]
    const float* bih  = (const float*)d_in[5];  // [4H]
    const float* bhh  = (const float*)d_in[6];  // [4H]
    const float* Wout = (const float*)d_in[7];  // [I, H]
    const float* bout = (const float*)d_in[8];  // [I]
    float* out = (float*)d_out;

    for (int t = 0; t < LSEQ; t++) {
        int w = t & 1;
        int r = w ^ 1;
        lstm_step<<<128, 128>>>(
            x + (size_t)t * NB * IDIM,
            (t == 0) ? h0 : nullptr,
            (t == 0) ? c0 : nullptr,
            Wih, Whh, bih, bhh, r, w);
    }
    int final_buf = (LSEQ - 1) & 1;  // = 1
    dim3 yg(IDIM / 128, NB);
    out_proj<<<yg, 128>>>(Wout, bout, out, final_buf);
    copy_hc<<<(NB * HDIM) / 256, 256>>>(out, final_buf);
}

// round 6
// speedup vs baseline: 3.4287x; 3.4287x over previous
#include <cuda_runtime.h>
#include <cuda_bf16.h>
#include <math.h>
#include <stdint.h>

// ---------------- problem dims ----------------
#define LSEQ 512
#define NB   64
#define IDIM 1024
#define HDIM 1024
#define KTOT 2048
#define NBLK 128          // step grid: one 32-z-col tile per block
#define HC   8            // hidden cols per block
#define ZC   32           // z-cols per block (4 gates x HC)
#define KB   64           // K chunk
#define NCHUNK 32
#define LDA  144          // smem row stride in bytes (16B-aligned, LDSM conflict-free)

// smem: A tiles [buf][split] 64x144, B tiles [buf][split] 32x144
#define A_TILE (64 * LDA)            // 9216
#define B_TILE (32 * LDA)            // 4608
#define OFF_B  (4 * A_TILE)          // 36864
#define SMEM_BYTES (4 * A_TILE + 4 * B_TILE)   // 55296

// ---------------- device scratch (static; no allocation) ----------------
__device__ __nv_bfloat16 gW_hi[NBLK * ZC * KTOT];   // block-major [blk][zrow32][k2048]
__device__ __nv_bfloat16 gW_lo[NBLK * ZC * KTOT];
__device__ float         gB[4 * HDIM];
__device__ __nv_bfloat16 gX_hi[LSEQ * NB * IDIM];   // pre-split x
__device__ __nv_bfloat16 gX_lo[LSEQ * NB * IDIM];
__device__ __nv_bfloat16 gH_hi[2][NB * HDIM];       // h ping-pong
__device__ __nv_bfloat16 gH_lo[2][NB * HDIM];
__device__ float         g_c [NB * HDIM];
__device__ float         g_hf[NB * HDIM];

// ---------------- helpers ----------------
__device__ __forceinline__ uint32_t smem_u32(const void* p) {
    uint32_t a;
    asm("{ .reg .u64 t; cvta.to.shared.u64 t, %1; cvt.u32.u64 %0, t; }" : "=r"(a) : "l"(p));
    return a;
}
__device__ __forceinline__ void cp16(uint32_t dst, const void* src) {
    asm volatile("cp.async.cg.shared.global [%0], [%1], 16;"
                 :: "r"(dst), "l"(__cvta_generic_to_global(src)));
}
__device__ __forceinline__ void ldsm4(uint32_t& r0, uint32_t& r1, uint32_t& r2,
                                      uint32_t& r3, uint32_t a) {
    asm volatile("ldmatrix.sync.aligned.m8n8.x4.shared.b16 {%0,%1,%2,%3}, [%4];"
                 : "=r"(r0), "=r"(r1), "=r"(r2), "=r"(r3) : "r"(a));
}
__device__ __forceinline__ void mma16816(float* c,
                                         uint32_t a0, uint32_t a1, uint32_t a2, uint32_t a3,
                                         uint32_t b0, uint32_t b1) {
    asm volatile(
        "mma.sync.aligned.m16n8k16.row.col.f32.bf16.bf16.f32 "
        "{%0,%1,%2,%3},{%4,%5,%6,%7},{%8,%9},{%0,%1,%2,%3};"
        : "+f"(c[0]), "+f"(c[1]), "+f"(c[2]), "+f"(c[3])
        : "r"(a0), "r"(a1), "r"(a2), "r"(a3), "r"(b0), "r"(b1));
}
__device__ __forceinline__ void split_bf16(float v, __nv_bfloat16& hi, __nv_bfloat16& lo) {
    hi = __float2bfloat16(v);
    lo = __float2bfloat16(v - __bfloat162float(hi));
}

// ---------------- prep kernels ----------------
__global__ __launch_bounds__(256) void prep_w(
    const float* __restrict__ Wih, const float* __restrict__ Whh,
    const float* __restrict__ bih, const float* __restrict__ bhh)
{
    int d  = blockIdx.x * 256 + threadIdx.x;         // 0 .. 8388607
    int b  = d >> 16;
    int rr = (d >> 11) & 31;
    int k  = d & 2047;
    int zc = ((rr >> 3) << 10) + b * HC + (rr & 7);
    float w = (k < IDIM) ? Wih[zc * IDIM + k] : Whh[zc * HDIM + (k - IDIM)];
    __nv_bfloat16 hi, lo; split_bf16(w, hi, lo);
    gW_hi[d] = hi; gW_lo[d] = lo;
    if (d < 4 * HDIM) gB[d] = bih[d] + bhh[d];
}

__global__ __launch_bounds__(256) void prep_x(const float* __restrict__ x)
{
    size_t idx = (size_t)blockIdx.x * 256 + threadIdx.x;  // 0 .. 33554431
    __nv_bfloat16 hi, lo; split_bf16(x[idx], hi, lo);
    gX_hi[idx] = hi; gX_lo[idx] = lo;
}

__global__ __launch_bounds__(256) void init_h(
    const float* __restrict__ h0, const float* __restrict__ c0)
{
    int idx = blockIdx.x * 256 + threadIdx.x;        // 0..65535
    __nv_bfloat16 hi, lo; split_bf16(h0[idx], hi, lo);
    gH_hi[0][idx] = hi; gH_lo[0][idx] = lo;
    g_c[idx] = c0[idx];
}

// ---------------- per-step kernel (HMMA) ----------------
__global__ __launch_bounds__(128, 1) void lstm_step_mma(int t, int rd, int wr)
{
    extern __shared__ char sm[];
    const uint32_t sb = smem_u32(sm);

    const int tid = threadIdx.x;
    const int w   = tid >> 5;
    const int l   = tid & 31;
    const int jh0 = blockIdx.x * HC;

    const __nv_bfloat16* __restrict__ xh  = gX_hi + (size_t)t * NB * IDIM;
    const __nv_bfloat16* __restrict__ xl  = gX_lo + (size_t)t * NB * IDIM;
    const __nv_bfloat16* __restrict__ Hhi = gH_hi[rd];
    const __nv_bfloat16* __restrict__ Hlo = gH_lo[rd];
    const __nv_bfloat16* __restrict__ Whi = gW_hi + (size_t)blockIdx.x * ZC * KTOT;
    const __nv_bfloat16* __restrict__ Wlo = gW_lo + (size_t)blockIdx.x * ZC * KTOT;

    float acc[4][4] = {};   // [gate/n8-tile][cfrag]

    // ---- chunk loader (12 cp16/thread) ----
    auto load_chunk = [&](int ch) {
        const int buf = ch & 1;
        const int k0  = ch * KB;
        const __nv_bfloat16* ah; const __nv_bfloat16* al;
        if (k0 < IDIM) { ah = xh + k0;           al = xl + k0; }
        else           { ah = Hhi + (k0 - IDIM); al = Hlo + (k0 - IDIM); }
        const uint32_t aH = sb + (buf * 2 + 0) * A_TILE;
        const uint32_t aL = sb + (buf * 2 + 1) * A_TILE;
        #pragma unroll
        for (int i = 0; i < 4; i++) {
            int s = tid + i * 128, r = s >> 3, sg = s & 7;
            uint32_t d = r * LDA + sg * 16;
            cp16(aH + d, ah + r * 1024 + sg * 8);
            cp16(aL + d, al + r * 1024 + sg * 8);
        }
        const uint32_t bH = sb + OFF_B + (buf * 2 + 0) * B_TILE;
        const uint32_t bL = sb + OFF_B + (buf * 2 + 1) * B_TILE;
        #pragma unroll
        for (int i = 0; i < 2; i++) {
            int s = tid + i * 128, r = s >> 3, sg = s & 7;
            uint32_t d = r * LDA + sg * 16;
            size_t  g = (size_t)r * KTOT + k0 + sg * 8;
            cp16(bH + d, Whi + g);
            cp16(bL + d, Wlo + g);
        }
        asm volatile("cp.async.commit_group;" ::: "memory");
    };

    // ldmatrix lane addressing
    const uint32_t rowA = w * 16 + (l & 7) + ((l >> 3) & 1) * 8;
    const uint32_t acol = (l >> 4) * 16;
    const uint32_t rowB = (l & 7) + (l >> 4) * 8;
    const uint32_t bcol = ((l >> 3) & 1) * 16;

    load_chunk(0);

    for (int ch = 0; ch < NCHUNK; ch++) {
        const int buf = ch & 1;
        if (ch + 1 < NCHUNK) {
            load_chunk(ch + 1);
            asm volatile("cp.async.wait_group 1;" ::: "memory");
        } else {
            asm volatile("cp.async.wait_group 0;" ::: "memory");
        }
        __syncthreads();

        const uint32_t aHb = sb + (buf * 2 + 0) * A_TILE + rowA * LDA + acol;
        const uint32_t aLb = sb + (buf * 2 + 1) * A_TILE + rowA * LDA + acol;
        const uint32_t bHb = sb + OFF_B + (buf * 2 + 0) * B_TILE + rowB * LDA + bcol;
        const uint32_t bLb = sb + OFF_B + (buf * 2 + 1) * B_TILE + rowB * LDA + bcol;

        #pragma unroll
        for (int ks = 0; ks < 4; ks++) {
            const uint32_t ko = ks * 32;
            uint32_t ah0, ah1, ah2, ah3, al0, al1, al2, al3;
            ldsm4(ah0, ah1, ah2, ah3, aHb + ko);
            ldsm4(al0, al1, al2, al3, aLb + ko);
            uint32_t bh[8], bl[8];
            ldsm4(bh[0], bh[1], bh[2], bh[3], bHb + ko);              // n-tiles 0,1
            ldsm4(bh[4], bh[5], bh[6], bh[7], bHb + 16 * LDA + ko);   // n-tiles 2,3
            ldsm4(bl[0], bl[1], bl[2], bl[3], bLb + ko);
            ldsm4(bl[4], bl[5], bl[6], bl[7], bLb + 16 * LDA + ko);
            #pragma unroll
            for (int tile = 0; tile < 4; tile++) {
                mma16816(acc[tile], ah0, ah1, ah2, ah3, bh[2 * tile], bh[2 * tile + 1]);
                mma16816(acc[tile], ah0, ah1, ah2, ah3, bl[2 * tile], bl[2 * tile + 1]);
                mma16816(acc[tile], al0, al1, al2, al3, bh[2 * tile], bh[2 * tile + 1]);
            }
        }
        __syncthreads();
    }

    // ---- epilogue: gates fuse in-register (tile index == gate) ----
    const int grp = l >> 2, tc = l & 3;
    #pragma unroll
    for (int j = 0; j < 4; j++) {
        int r   = w * 16 + grp + (j >> 1) * 8;
        int col = jh0 + tc * 2 + (j & 1);
        float zi = acc[0][j] + gB[col];
        float zf = acc[1][j] + gB[1024 + col];
        float zg = acc[2][j] + gB[2048 + col];
        float zo = acc[3][j] + gB[3072 + col];
        float cprev = g_c[r * HDIM + col];
        float ig = 1.0f / (1.0f + expf(-zi));
        float fg = 1.0f / (1.0f + expf(-zf));
        float og = 1.0f / (1.0f + expf(-zo));
        float gg = tanhf(zg);
        float cn = fg * cprev + ig * gg;
        g_c[r * HDIM + col] = cn;
        float hv = og * tanhf(cn);
        g_hf[r * HDIM + col] = hv;
        __nv_bfloat16 hi, lo; split_bf16(hv, hi, lo);
        gH_hi[wr][r * HDIM + col] = hi;
        gH_lo[wr][r * HDIM + col] = lo;
    }
}

// ---------------- final projection ----------------
__global__ __launch_bounds__(128) void out_proj(
    const float* __restrict__ Wout, const float* __restrict__ bout,
    float* __restrict__ y)
{
    int n = blockIdx.y;
    int i = blockIdx.x * 128 + threadIdx.x;
    __shared__ float hs[HDIM];
    for (int k = threadIdx.x; k < HDIM; k += 128) hs[k] = g_hf[n * HDIM + k];
    __syncthreads();
    float acc = bout[i];
    const float* wr = Wout + (size_t)i * HDIM;
    #pragma unroll 8
    for (int k = 0; k < HDIM; k++) acc += hs[k] * wr[k];
    y[n * IDIM + i] = acc;
}

__global__ void copy_hc(float* __restrict__ out)
{
    int idx = blockIdx.x * 256 + threadIdx.x;   // 65536
    out[NB * IDIM + idx]             = g_hf[idx];
    out[NB * IDIM + NB * HDIM + idx] = g_c[idx];
}

// ---------------- launch ----------------
extern "C" void kernel_launch(void* const* d_in, const int* in_sizes, int n_in,
                              void* d_out, int out_size)
{
    const float* x    = (const float*)d_in[0];
    const float* h0   = (const float*)d_in[1];
    const float* c0   = (const float*)d_in[2];
    const float* Wih  = (const float*)d_in[3];
    const float* Whh  = (const float*)d_in[4];
    const float* bih  = (const float*)d_in[5];
    const float* bhh  = (const float*)d_in[6];
    const float* Wout = (const float*)d_in[7];
    const float* bout = (const float*)d_in[8];
    float* out = (float*)d_out;

    cudaFuncSetAttribute(lstm_step_mma,
                         cudaFuncAttributeMaxDynamicSharedMemorySize, SMEM_BYTES);

    prep_w<<<(NBLK * ZC * KTOT) / 256, 256>>>(Wih, Whh, bih, bhh);
    prep_x<<<(LSEQ * NB * IDIM) / 256, 256>>>(x);
    init_h<<<(NB * HDIM) / 256, 256>>>(h0, c0);

    for (int t = 0; t < LSEQ; t++)
        lstm_step_mma<<<NBLK, 128, SMEM_BYTES>>>(t, t & 1, (t + 1) & 1);

    dim3 yg(IDIM / 128, NB);
    out_proj<<<yg, 128>>>(Wout, bout, out);
    copy_hc<<<(NB * HDIM) / 256, 256>>>(out);
}

// round 7
// speedup vs baseline: 3.5025x; 1.0215x over previous
#include <cuda_runtime.h>
#include <cuda_bf16.h>
#include <math.h>
#include <stdint.h>

// ---------------- problem dims ----------------
#define LSEQ 512
#define NB   64
#define IDIM 1024
#define HDIM 1024
#define KTOT 2048
#define NBLK 128          // step grid: one 32-z-col tile per block
#define HC   8            // hidden cols per block
#define ZC   32           // z-cols per block (4 gates x HC)
#define KB   64           // K chunk
#define NCHUNK 32
#define LDA  144          // smem row stride bytes (16B aligned, LDSM conflict-free)

#define A_TILE (64 * LDA)                 // 9216
#define B_TILE (32 * LDA)                 // 4608
#define STG    (2 * A_TILE + 2 * B_TILE)  // 27648 per pipeline stage
#define PIPE   3
#define SMEM_BYTES (PIPE * STG)           // 82944

// ---------------- device scratch (static; no allocation) ----------------
__device__ __nv_bfloat16 gW_hi[NBLK * ZC * KTOT];   // block-major [blk][zrow32][k2048]
__device__ __nv_bfloat16 gW_lo[NBLK * ZC * KTOT];
__device__ float         gB[4 * HDIM];
__device__ __nv_bfloat16 gX_hi[LSEQ * NB * IDIM];   // pre-split x
__device__ __nv_bfloat16 gX_lo[LSEQ * NB * IDIM];
__device__ __nv_bfloat16 gH_hi[2][NB * HDIM];       // h ping-pong
__device__ __nv_bfloat16 gH_lo[2][NB * HDIM];
__device__ float         g_c [NB * HDIM];
__device__ float         g_hf[NB * HDIM];

// ---------------- helpers ----------------
__device__ __forceinline__ uint32_t smem_u32(const void* p) {
    uint32_t a;
    asm("{ .reg .u64 t; cvta.to.shared.u64 t, %1; cvt.u32.u64 %0, t; }" : "=r"(a) : "l"(p));
    return a;
}
__device__ __forceinline__ void cp16(uint32_t dst, const void* src) {
    asm volatile("cp.async.cg.shared.global [%0], [%1], 16;"
                 :: "r"(dst), "l"(__cvta_generic_to_global(src)));
}
__device__ __forceinline__ void ldsm4(uint32_t& r0, uint32_t& r1, uint32_t& r2,
                                      uint32_t& r3, uint32_t a) {
    asm volatile("ldmatrix.sync.aligned.m8n8.x4.shared.b16 {%0,%1,%2,%3}, [%4];"
                 : "=r"(r0), "=r"(r1), "=r"(r2), "=r"(r3) : "r"(a));
}
__device__ __forceinline__ void mma16816(float* c,
                                         uint32_t a0, uint32_t a1, uint32_t a2, uint32_t a3,
                                         uint32_t b0, uint32_t b1) {
    asm volatile(
        "mma.sync.aligned.m16n8k16.row.col.f32.bf16.bf16.f32 "
        "{%0,%1,%2,%3},{%4,%5,%6,%7},{%8,%9},{%0,%1,%2,%3};"
        : "+f"(c[0]), "+f"(c[1]), "+f"(c[2]), "+f"(c[3])
        : "r"(a0), "r"(a1), "r"(a2), "r"(a3), "r"(b0), "r"(b1));
}
__device__ __forceinline__ void split_bf16(float v, __nv_bfloat16& hi, __nv_bfloat16& lo) {
    hi = __float2bfloat16(v);
    lo = __float2bfloat16(v - __bfloat162float(hi));
}

// ---------------- prep kernels ----------------
__global__ __launch_bounds__(256) void prep_w(
    const float* __restrict__ Wih, const float* __restrict__ Whh,
    const float* __restrict__ bih, const float* __restrict__ bhh)
{
    int d  = blockIdx.x * 256 + threadIdx.x;         // 0 .. 8388607
    int b  = d >> 16;
    int rr = (d >> 11) & 31;
    int k  = d & 2047;
    int zc = ((rr >> 3) << 10) + b * HC + (rr & 7);
    float w = (k < IDIM) ? Wih[zc * IDIM + k] : Whh[zc * HDIM + (k - IDIM)];
    __nv_bfloat16 hi, lo; split_bf16(w, hi, lo);
    gW_hi[d] = hi; gW_lo[d] = lo;
    if (d < 4 * HDIM) gB[d] = bih[d] + bhh[d];
}

__global__ __launch_bounds__(256) void prep_x(const float* __restrict__ x)
{
    size_t idx = (size_t)blockIdx.x * 256 + threadIdx.x;
    __nv_bfloat16 hi, lo; split_bf16(x[idx], hi, lo);
    gX_hi[idx] = hi; gX_lo[idx] = lo;
}

__global__ __launch_bounds__(256) void init_h(
    const float* __restrict__ h0, const float* __restrict__ c0)
{
    int idx = blockIdx.x * 256 + threadIdx.x;
    __nv_bfloat16 hi, lo; split_bf16(h0[idx], hi, lo);
    gH_hi[0][idx] = hi; gH_lo[0][idx] = lo;
    g_c[idx] = c0[idx];
}

// ---------------- per-step kernel (HMMA, 8 warps) ----------------
__global__ __launch_bounds__(256, 1) void lstm_step_mma(int t, int rd, int wr)
{
    extern __shared__ char sm[];
    const uint32_t sb = smem_u32(sm);

    const int tid = threadIdx.x;
    const int w   = tid >> 5;
    const int l   = tid & 31;
    const int wm  = w & 3;          // M part: rows wm*16..+15
    const int wn  = w >> 2;         // N half: cols wn*16..+15
    const int jh0 = blockIdx.x * HC;

    const __nv_bfloat16* __restrict__ xh  = gX_hi + (size_t)t * NB * IDIM;
    const __nv_bfloat16* __restrict__ xl  = gX_lo + (size_t)t * NB * IDIM;
    const __nv_bfloat16* __restrict__ Hhi = gH_hi[rd];
    const __nv_bfloat16* __restrict__ Hlo = gH_lo[rd];
    const __nv_bfloat16* __restrict__ Whi = gW_hi + (size_t)blockIdx.x * ZC * KTOT;
    const __nv_bfloat16* __restrict__ Wlo = gW_lo + (size_t)blockIdx.x * ZC * KTOT;

    float acc[2][4] = {};   // two n8 tiles (cols wn*16+{0..7}, {8..15})

    auto load_chunk = [&](int ch) {
        const int buf = ch - (ch / PIPE) * PIPE;
        const uint32_t st = sb + buf * STG;
        const int k0 = ch * KB;
        const __nv_bfloat16* ah; const __nv_bfloat16* al;
        if (k0 < IDIM) { ah = xh + k0;           al = xl + k0; }
        else           { ah = Hhi + (k0 - IDIM); al = Hlo + (k0 - IDIM); }
        #pragma unroll
        for (int i = 0; i < 2; i++) {            // A hi/lo: 512 float4 each
            int s = tid + i * 256, r = s >> 3, sg = s & 7;
            uint32_t d = r * LDA + sg * 16;
            cp16(st + d,          ah + r * 1024 + sg * 8);
            cp16(st + A_TILE + d, al + r * 1024 + sg * 8);
        }
        {                                        // B hi/lo: 256 float4 each
            int r = tid >> 3, sg = tid & 7;
            uint32_t d = r * LDA + sg * 16;
            size_t  g = (size_t)r * KTOT + k0 + sg * 8;
            cp16(st + 2 * A_TILE + d,          Whi + g);
            cp16(st + 2 * A_TILE + B_TILE + d, Wlo + g);
        }
        asm volatile("cp.async.commit_group;" ::: "memory");
    };

    // ldmatrix lane addressing (x4 layout: lanes/8 -> matrix 0..3)
    const uint32_t rowA = wm * 16 + (l & 7) + ((l >> 3) & 1) * 8;
    const uint32_t acol = (l >> 4) * 16;
    const uint32_t rowB = wn * 16 + (l & 7) + ((l >> 4) & 1) * 8;
    const uint32_t bcol = ((l >> 3) & 1) * 16;

    load_chunk(0);
    load_chunk(1);

    for (int ch = 0; ch < NCHUNK; ch++) {
        if (ch < NCHUNK - 1)
            asm volatile("cp.async.wait_group 1;" ::: "memory");
        else
            asm volatile("cp.async.wait_group 0;" ::: "memory");
        __syncthreads();
        if (ch + 2 < NCHUNK) load_chunk(ch + 2);

        const int buf = ch - (ch / PIPE) * PIPE;
        const uint32_t st  = sb + buf * STG;
        const uint32_t aHb = st + rowA * LDA + acol;
        const uint32_t aLb = aHb + A_TILE;
        const uint32_t bHb = st + 2 * A_TILE + rowB * LDA + bcol;
        const uint32_t bLb = bHb + B_TILE;

        #pragma unroll
        for (int ks = 0; ks < 4; ks++) {
            const uint32_t ko = ks * 32;
            uint32_t ah0, ah1, ah2, ah3, al0, al1, al2, al3;
            uint32_t bh0, bh1, bh2, bh3, bl0, bl1, bl2, bl3;
            ldsm4(ah0, ah1, ah2, ah3, aHb + ko);
            ldsm4(al0, al1, al2, al3, aLb + ko);
            ldsm4(bh0, bh1, bh2, bh3, bHb + ko);
            ldsm4(bl0, bl1, bl2, bl3, bLb + ko);
            // term-major order: same-acc reuse distance = 2
            mma16816(acc[0], ah0, ah1, ah2, ah3, bh0, bh1);
            mma16816(acc[1], ah0, ah1, ah2, ah3, bh2, bh3);
            mma16816(acc[0], ah0, ah1, ah2, ah3, bl0, bl1);
            mma16816(acc[1], ah0, ah1, ah2, ah3, bl2, bl3);
            mma16816(acc[0], al0, al1, al2, al3, bh0, bh1);
            mma16816(acc[1], al0, al1, al2, al3, bh2, bh3);
        }
    }

    // ---- epilogue: stage z in smem (reuse stage buffers), fuse gates ----
    __syncthreads();
    float* zs = (float*)sm;   // [64][33]
    #pragma unroll
    for (int tl = 0; tl < 2; tl++)
        #pragma unroll
        for (int j = 0; j < 4; j++) {
            int r = wm * 16 + (l >> 2) + (j >> 1) * 8;
            int c = wn * 16 + tl * 8 + (l & 3) * 2 + (j & 1);
            zs[r * 33 + c] = acc[tl][j];
        }
    __syncthreads();

    #pragma unroll
    for (int u = 0; u < 2; u++) {
        int idx = tid * 2 + u;          // 0..511
        int r = idx >> 3, hid = idx & 7;
        int col = jh0 + hid;
        float zi = zs[r * 33 + hid]      + gB[col];
        float zf = zs[r * 33 + 8 + hid]  + gB[1024 + col];
        float zg = zs[r * 33 + 16 + hid] + gB[2048 + col];
        float zo = zs[r * 33 + 24 + hid] + gB[3072 + col];
        float cprev = g_c[r * HDIM + col];
        float ig = 1.0f / (1.0f + expf(-zi));
        float fg = 1.0f / (1.0f + expf(-zf));
        float og = 1.0f / (1.0f + expf(-zo));
        float gg = tanhf(zg);
        float cn = fg * cprev + ig * gg;
        g_c[r * HDIM + col] = cn;
        float hv = og * tanhf(cn);
        g_hf[r * HDIM + col] = hv;
        __nv_bfloat16 hi, lo; split_bf16(hv, hi, lo);
        gH_hi[wr][r * HDIM + col] = hi;
        gH_lo[wr][r * HDIM + col] = lo;
    }
}

// ---------------- final projection ----------------
__global__ __launch_bounds__(128) void out_proj(
    const float* __restrict__ Wout, const float* __restrict__ bout,
    float* __restrict__ y)
{
    int n = blockIdx.y;
    int i = blockIdx.x * 128 + threadIdx.x;
    __shared__ float hs[HDIM];
    for (int k = threadIdx.x; k < HDIM; k += 128) hs[k] = g_hf[n * HDIM + k];
    __syncthreads();
    float acc = bout[i];
    const float* wrow = Wout + (size_t)i * HDIM;
    #pragma unroll 8
    for (int k = 0; k < HDIM; k++) acc += hs[k] * wrow[k];
    y[n * IDIM + i] = acc;
}

__global__ void copy_hc(float* __restrict__ out)
{
    int idx = blockIdx.x * 256 + threadIdx.x;
    out[NB * IDIM + idx]             = g_hf[idx];
    out[NB * IDIM + NB * HDIM + idx] = g_c[idx];
}

// ---------------- launch ----------------
extern "C" void kernel_launch(void* const* d_in, const int* in_sizes, int n_in,
                              void* d_out, int out_size)
{
    const float* x    = (const float*)d_in[0];
    const float* h0   = (const float*)d_in[1];
    const float* c0   = (const float*)d_in[2];
    const float* Wih  = (const float*)d_in[3];
    const float* Whh  = (const float*)d_in[4];
    const float* bih  = (const float*)d_in[5];
    const float* bhh  = (const float*)d_in[6];
    const float* Wout = (const float*)d_in[7];
    const float* bout = (const float*)d_in[8];
    float* out = (float*)d_out;

    cudaFuncSetAttribute(lstm_step_mma,
                         cudaFuncAttributeMaxDynamicSharedMemorySize, SMEM_BYTES);

    prep_w<<<(NBLK * ZC * KTOT) / 256, 256>>>(Wih, Whh, bih, bhh);
    prep_x<<<(LSEQ * NB * IDIM) / 256, 256>>>(x);
    init_h<<<(NB * HDIM) / 256, 256>>>(h0, c0);

    for (int t = 0; t < LSEQ; t++)
        lstm_step_mma<<<NBLK, 256, SMEM_BYTES>>>(t, t & 1, (t + 1) & 1);

    dim3 yg(IDIM / 128, NB);
    out_proj<<<yg, 128>>>(Wout, bout, out);
    copy_hc<<<(NB * HDIM) / 256, 256>>>(out);
}

// round 8
// speedup vs baseline: 4.4048x; 1.2576x over previous
#include <cuda_runtime.h>
#include <cuda_bf16.h>
#include <math.h>
#include <stdint.h>

// ---------------- problem dims ----------------
#define LSEQ 512
#define NB   64
#define IDIM 1024
#define HDIM 1024
#define KTOT 2048
#define NBLK 128          // step grid: one 32-z-col tile per block
#define HC   8            // hidden cols per block
#define ZC   32           // z-cols per block (4 gates x HC)
#define KB   64           // K chunk
#define NCHUNK 32
#define NGRP 4            // K-groups (2 warps each)
#define CPG  (NCHUNK / NGRP)   // chunks per group = 8
#define LDA  144          // smem row stride bytes (16B aligned, LDSM conflict-free)

#define A_TILE (64 * LDA)                 // 9216
#define B_TILE (32 * LDA)                 // 4608
#define STG    (2 * A_TILE + 2 * B_TILE)  // 27648 per stage
#define SMEM_BYTES (NGRP * 2 * STG)       // 221184 (2 stages per group)

// ---------------- device scratch (static; no allocation) ----------------
__device__ __nv_bfloat16 gW_hi[NBLK * ZC * KTOT];   // block-major [blk][zrow32][k2048]
__device__ __nv_bfloat16 gW_lo[NBLK * ZC * KTOT];
__device__ float         gB[4 * HDIM];
__device__ __nv_bfloat16 gX_hi[LSEQ * NB * IDIM];   // pre-split x
__device__ __nv_bfloat16 gX_lo[LSEQ * NB * IDIM];
__device__ __nv_bfloat16 gH_hi[2][NB * HDIM];       // h ping-pong
__device__ __nv_bfloat16 gH_lo[2][NB * HDIM];
__device__ float         g_c [NB * HDIM];
__device__ float         g_hf[NB * HDIM];

// ---------------- helpers ----------------
__device__ __forceinline__ uint32_t smem_u32(const void* p) {
    uint32_t a;
    asm("{ .reg .u64 t; cvta.to.shared.u64 t, %1; cvt.u32.u64 %0, t; }" : "=r"(a) : "l"(p));
    return a;
}
__device__ __forceinline__ void cp16(uint32_t dst, const void* src) {
    asm volatile("cp.async.cg.shared.global [%0], [%1], 16;"
                 :: "r"(dst), "l"(__cvta_generic_to_global(src)));
}
__device__ __forceinline__ void ldsm4(uint32_t* r, uint32_t a) {
    asm volatile("ldmatrix.sync.aligned.m8n8.x4.shared.b16 {%0,%1,%2,%3}, [%4];"
                 : "=r"(r[0]), "=r"(r[1]), "=r"(r[2]), "=r"(r[3]) : "r"(a));
}
__device__ __forceinline__ void mma16816(float* c, const uint32_t* a,
                                         uint32_t b0, uint32_t b1) {
    asm volatile(
        "mma.sync.aligned.m16n8k16.row.col.f32.bf16.bf16.f32 "
        "{%0,%1,%2,%3},{%4,%5,%6,%7},{%8,%9},{%0,%1,%2,%3};"
        : "+f"(c[0]), "+f"(c[1]), "+f"(c[2]), "+f"(c[3])
        : "r"(a[0]), "r"(a[1]), "r"(a[2]), "r"(a[3]), "r"(b0), "r"(b1));
}
__device__ __forceinline__ void split_bf16(float v, __nv_bfloat16& hi, __nv_bfloat16& lo) {
    hi = __float2bfloat16(v);
    lo = __float2bfloat16(v - __bfloat162float(hi));
}

// ---------------- prep kernels ----------------
__global__ __launch_bounds__(256) void prep_w(
    const float* __restrict__ Wih, const float* __restrict__ Whh,
    const float* __restrict__ bih, const float* __restrict__ bhh)
{
    int d  = blockIdx.x * 256 + threadIdx.x;         // 0 .. 8388607
    int b  = d >> 16;
    int rr = (d >> 11) & 31;
    int k  = d & 2047;
    int zc = ((rr >> 3) << 10) + b * HC + (rr & 7);
    float w = (k < IDIM) ? Wih[zc * IDIM + k] : Whh[zc * HDIM + (k - IDIM)];
    __nv_bfloat16 hi, lo; split_bf16(w, hi, lo);
    gW_hi[d] = hi; gW_lo[d] = lo;
    if (d < 4 * HDIM) gB[d] = bih[d] + bhh[d];
}

__global__ __launch_bounds__(256) void prep_x(const float* __restrict__ x)
{
    size_t idx = (size_t)blockIdx.x * 256 + threadIdx.x;
    __nv_bfloat16 hi, lo; split_bf16(x[idx], hi, lo);
    gX_hi[idx] = hi; gX_lo[idx] = lo;
}

__global__ __launch_bounds__(256) void init_h(
    const float* __restrict__ h0, const float* __restrict__ c0)
{
    int idx = blockIdx.x * 256 + threadIdx.x;
    __nv_bfloat16 hi, lo; split_bf16(h0[idx], hi, lo);
    gH_hi[0][idx] = hi; gH_lo[0][idx] = lo;
    g_c[idx] = c0[idx];
}

// ---------------- per-step kernel (HMMA, 8 warps, 4 K-groups) ----------------
__global__ __launch_bounds__(256, 1) void lstm_step_mma(int t, int rd, int wr)
{
    extern __shared__ char sm[];
    const uint32_t sb = smem_u32(sm);

    const int tid = threadIdx.x;
    const int w   = tid >> 5;
    const int l   = tid & 31;
    const int g   = w >> 1;          // K-group 0..3
    const int wg  = w & 1;           // warp-in-group: rows wg*32..+31
    const int gt  = tid & 63;        // thread-in-group
    const int jh0 = blockIdx.x * HC;

    const __nv_bfloat16* __restrict__ xh  = gX_hi + (size_t)t * NB * IDIM;
    const __nv_bfloat16* __restrict__ xl  = gX_lo + (size_t)t * NB * IDIM;
    const __nv_bfloat16* __restrict__ Hhi = gH_hi[rd];
    const __nv_bfloat16* __restrict__ Hlo = gH_lo[rd];
    const __nv_bfloat16* __restrict__ Whi = gW_hi + (size_t)blockIdx.x * ZC * KTOT;
    const __nv_bfloat16* __restrict__ Wlo = gW_lo + (size_t)blockIdx.x * ZC * KTOT;

    float acc[2][4][4] = {};   // [m16 tile][n8 tile][frag]

    // group-local chunk loader: 24 cp16 per thread
    auto load_chunk = [&](int ch, int pb) {
        const uint32_t st = sb + (g * 2 + pb) * STG;
        const int k0 = ch * KB;
        const __nv_bfloat16* ah; const __nv_bfloat16* al;
        if (k0 < IDIM) { ah = xh + k0;           al = xl + k0; }
        else           { ah = Hhi + (k0 - IDIM); al = Hlo + (k0 - IDIM); }
        #pragma unroll
        for (int i = 0; i < 8; i++) {            // A hi/lo: 512 float4 each
            int s = gt + i * 64, r = s >> 3, sg = s & 7;
            uint32_t d = r * LDA + sg * 16;
            cp16(st + d,          ah + r * 1024 + sg * 8);
            cp16(st + A_TILE + d, al + r * 1024 + sg * 8);
        }
        #pragma unroll
        for (int i = 0; i < 4; i++) {            // B hi/lo: 256 float4 each
            int s = gt + i * 64, r = s >> 3, sg = s & 7;
            uint32_t d = r * LDA + sg * 16;
            size_t  gb = (size_t)r * KTOT + k0 + sg * 8;
            cp16(st + 2 * A_TILE + d,          Whi + gb);
            cp16(st + 2 * A_TILE + B_TILE + d, Wlo + gb);
        }
        asm volatile("cp.async.commit_group;" ::: "memory");
    };

    // ldmatrix lane addressing
    const uint32_t rowA = wg * 32 + (l & 7) + ((l >> 3) & 1) * 8;
    const uint32_t acol = (l >> 4) * 16;
    const uint32_t rowB = (l & 7) + ((l >> 4) & 1) * 8;
    const uint32_t bcol = ((l >> 3) & 1) * 16;

    load_chunk(g, 0);

    for (int i = 0; i < CPG; i++) {
        const int ch = g + i * NGRP;
        asm volatile("cp.async.wait_group 0;" ::: "memory");
        asm volatile("bar.sync %0, %1;" :: "r"(g + 1), "r"(64) : "memory");
        if (i + 1 < CPG) load_chunk(ch + NGRP, (i + 1) & 1);

        const uint32_t st  = sb + (g * 2 + (i & 1)) * STG;
        const uint32_t aHb = st + rowA * LDA + acol;
        const uint32_t aLb = aHb + A_TILE;
        const uint32_t bHb = st + 2 * A_TILE + rowB * LDA + bcol;
        const uint32_t bLb = bHb + B_TILE;

        #pragma unroll
        for (int ks = 0; ks < 4; ks++) {
            const uint32_t ko = ks * 32;
            uint32_t ah[2][4], al[2][4], bh[2][4], bl[2][4];
            ldsm4(ah[0], aHb + ko);
            ldsm4(ah[1], aHb + 16 * LDA + ko);
            ldsm4(al[0], aLb + ko);
            ldsm4(al[1], aLb + 16 * LDA + ko);
            ldsm4(bh[0], bHb + ko);
            ldsm4(bh[1], bHb + 16 * LDA + ko);
            ldsm4(bl[0], bLb + ko);
            ldsm4(bl[1], bLb + 16 * LDA + ko);
            // term-major: same-acc reuse distance = 8
            #pragma unroll
            for (int mt = 0; mt < 2; mt++)
                #pragma unroll
                for (int nt = 0; nt < 4; nt++)
                    mma16816(acc[mt][nt], ah[mt], bh[nt >> 1][(nt & 1) * 2],
                             bh[nt >> 1][(nt & 1) * 2 + 1]);
            #pragma unroll
            for (int mt = 0; mt < 2; mt++)
                #pragma unroll
                for (int nt = 0; nt < 4; nt++)
                    mma16816(acc[mt][nt], ah[mt], bl[nt >> 1][(nt & 1) * 2],
                             bl[nt >> 1][(nt & 1) * 2 + 1]);
            #pragma unroll
            for (int mt = 0; mt < 2; mt++)
                #pragma unroll
                for (int nt = 0; nt < 4; nt++)
                    mma16816(acc[mt][nt], al[mt], bh[nt >> 1][(nt & 1) * 2],
                             bh[nt >> 1][(nt & 1) * 2 + 1]);
        }
    }

    // ---- epilogue: 4 K-partials -> smem -> reduce + gates ----
    __syncthreads();                        // stages dead; reuse for z planes
    float* zs = (float*)sm;                 // [4][64][33]
    const int zb = g * (64 * 33);
    #pragma unroll
    for (int mt = 0; mt < 2; mt++)
        #pragma unroll
        for (int nt = 0; nt < 4; nt++)
            #pragma unroll
            for (int j = 0; j < 4; j++) {
                int r = wg * 32 + mt * 16 + (l >> 2) + (j >> 1) * 8;
                int c = nt * 8 + (l & 3) * 2 + (j & 1);
                zs[zb + r * 33 + c] = acc[mt][nt][j];
            }
    __syncthreads();

    #pragma unroll
    for (int u = 0; u < 2; u++) {
        int idx = tid * 2 + u;              // 0..511
        int r = idx >> 3, hid = idx & 7;
        int col = jh0 + hid;
        float zi = gB[col], zf = gB[1024 + col], zg = gB[2048 + col], zo = gB[3072 + col];
        #pragma unroll
        for (int q = 0; q < 4; q++) {
            const float* p = zs + q * (64 * 33) + r * 33;
            zi += p[hid]; zf += p[8 + hid]; zg += p[16 + hid]; zo += p[24 + hid];
        }
        float cprev = g_c[r * HDIM + col];
        float ig = 1.0f / (1.0f + expf(-zi));
        float fg = 1.0f / (1.0f + expf(-zf));
        float og = 1.0f / (1.0f + expf(-zo));
        float gg = tanhf(zg);
        float cn = fg * cprev + ig * gg;
        g_c[r * HDIM + col] = cn;
        float hv = og * tanhf(cn);
        g_hf[r * HDIM + col] = hv;
        __nv_bfloat16 hi, lo; split_bf16(hv, hi, lo);
        gH_hi[wr][r * HDIM + col] = hi;
        gH_lo[wr][r * HDIM + col] = lo;
    }
}

// ---------------- final projection ----------------
__global__ __launch_bounds__(128) void out_proj(
    const float* __restrict__ Wout, const float* __restrict__ bout,
    float* __restrict__ y)
{
    int n = blockIdx.y;
    int i = blockIdx.x * 128 + threadIdx.x;
    __shared__ float hs[HDIM];
    for (int k = threadIdx.x; k < HDIM; k += 128) hs[k] = g_hf[n * HDIM + k];
    __syncthreads();
    float acc = bout[i];
    const float* wrow = Wout + (size_t)i * HDIM;
    #pragma unroll 8
    for (int k = 0; k < HDIM; k++) acc += hs[k] * wrow[k];
    y[n * IDIM + i] = acc;
}

__global__ void copy_hc(float* __restrict__ out)
{
    int idx = blockIdx.x * 256 + threadIdx.x;
    out[NB * IDIM + idx]             = g_hf[idx];
    out[NB * IDIM + NB * HDIM + idx] = g_c[idx];
}

// ---------------- launch ----------------
extern "C" void kernel_launch(void* const* d_in, const int* in_sizes, int n_in,
                              void* d_out, int out_size)
{
    const float* x    = (const float*)d_in[0];
    const float* h0   = (const float*)d_in[1];
    const float* c0   = (const float*)d_in[2];
    const float* Wih  = (const float*)d_in[3];
    const float* Whh  = (const float*)d_in[4];
    const float* bih  = (const float*)d_in[5];
    const float* bhh  = (const float*)d_in[6];
    const float* Wout = (const float*)d_in[7];
    const float* bout = (const float*)d_in[8];
    float* out = (float*)d_out;

    cudaFuncSetAttribute(lstm_step_mma,
                         cudaFuncAttributeMaxDynamicSharedMemorySize, SMEM_BYTES);

    prep_w<<<(NBLK * ZC * KTOT) / 256, 256>>>(Wih, Whh, bih, bhh);
    prep_x<<<(LSEQ * NB * IDIM) / 256, 256>>>(x);
    init_h<<<(NB * HDIM) / 256, 256>>>(h0, c0);

    for (int t = 0; t < LSEQ; t++)
        lstm_step_mma<<<NBLK, 256, SMEM_BYTES>>>(t, t & 1, (t + 1) & 1);

    dim3 yg(IDIM / 128, NB);
    out_proj<<<yg, 128>>>(Wout, bout, out);
    copy_hc<<<(NB * HDIM) / 256, 256>>>(out);
}

// round 9
// speedup vs baseline: 4.7994x; 1.0896x over previous
#include <cuda_runtime.h>
#include <cuda_bf16.h>
#include <math.h>
#include <stdint.h>

// ---------------- problem dims ----------------
#define LSEQ 512
#define NB   64
#define IDIM 1024
#define HDIM 1024
#define KTOT 2048
#define NBLK 128          // step grid: one 32-z-col tile per block
#define HC   8            // hidden cols per block
#define ZC   32           // z-cols per block (4 gates x HC)
#define KB   64           // K chunk
#define KH   1024         // per-step K (h-part only)
#define NCHUNK (KH / KB)  // 16
#define NGRP 4            // K-groups (2 warps each)
#define CPG  (NCHUNK / NGRP)   // 4
#define LDA  144          // smem row stride bytes (16B aligned, LDSM conflict-free)

#define A_TILE (64 * LDA)                 // 9216
#define B_TILE (32 * LDA)                 // 4608
#define STG    (2 * A_TILE + 2 * B_TILE)  // 27648 per stage
#define SMEM_BYTES (NGRP * 2 * STG)       // 221184

// zx precompute GEMM tiling
#define P_LDA 144
#define P_TILE (128 * P_LDA)              // 18432 per 128-row split tile
#define P_STG  (4 * P_TILE)               // A hi/lo + B hi/lo = 73728
#define P_SMEM (2 * P_STG)                // 147456

// ---------------- device scratch (static; no allocation) ----------------
__device__ __nv_bfloat16 gW_hi[NBLK * ZC * KTOT];   // block-major [blk][zrow32][k2048]
__device__ __nv_bfloat16 gW_lo[NBLK * ZC * KTOT];
__device__ float         gB[4 * HDIM];
__device__ __nv_bfloat16 gX_hi[LSEQ * NB * IDIM];   // pre-split x
__device__ __nv_bfloat16 gX_lo[LSEQ * NB * IDIM];
__device__ __nv_bfloat16 gH_hi[2][NB * HDIM];       // h ping-pong
__device__ __nv_bfloat16 gH_lo[2][NB * HDIM];
__device__ float         g_c [NB * HDIM];
__device__ float         g_hf[NB * HDIM];
__device__ float         g_zx[(size_t)LSEQ * NBLK * 64 * 32];  // x-part of z, tile order

// ---------------- helpers ----------------
__device__ __forceinline__ uint32_t smem_u32(const void* p) {
    uint32_t a;
    asm("{ .reg .u64 t; cvta.to.shared.u64 t, %1; cvt.u32.u64 %0, t; }" : "=r"(a) : "l"(p));
    return a;
}
__device__ __forceinline__ void cp16(uint32_t dst, const void* src) {
    asm volatile("cp.async.cg.shared.global [%0], [%1], 16;"
                 :: "r"(dst), "l"(__cvta_generic_to_global(src)));
}
__device__ __forceinline__ void ldsm4(uint32_t* r, uint32_t a) {
    asm volatile("ldmatrix.sync.aligned.m8n8.x4.shared.b16 {%0,%1,%2,%3}, [%4];"
                 : "=r"(r[0]), "=r"(r[1]), "=r"(r[2]), "=r"(r[3]) : "r"(a));
}
__device__ __forceinline__ void mma16816(float* c, const uint32_t* a,
                                         uint32_t b0, uint32_t b1) {
    asm volatile(
        "mma.sync.aligned.m16n8k16.row.col.f32.bf16.bf16.f32 "
        "{%0,%1,%2,%3},{%4,%5,%6,%7},{%8,%9},{%0,%1,%2,%3};"
        : "+f"(c[0]), "+f"(c[1]), "+f"(c[2]), "+f"(c[3])
        : "r"(a[0]), "r"(a[1]), "r"(a[2]), "r"(a[3]), "r"(b0), "r"(b1));
}
__device__ __forceinline__ void split_bf16(float v, __nv_bfloat16& hi, __nv_bfloat16& lo) {
    hi = __float2bfloat16(v);
    lo = __float2bfloat16(v - __bfloat162float(hi));
}

// ---------------- prep kernels ----------------
__global__ __launch_bounds__(256) void prep_w(
    const float* __restrict__ Wih, const float* __restrict__ Whh,
    const float* __restrict__ bih, const float* __restrict__ bhh)
{
    int d  = blockIdx.x * 256 + threadIdx.x;         // 0 .. 8388607
    int b  = d >> 16;
    int rr = (d >> 11) & 31;
    int k  = d & 2047;
    int zc = ((rr >> 3) << 10) + b * HC + (rr & 7);
    float w = (k < IDIM) ? Wih[zc * IDIM + k] : Whh[zc * HDIM + (k - IDIM)];
    __nv_bfloat16 hi, lo; split_bf16(w, hi, lo);
    gW_hi[d] = hi; gW_lo[d] = lo;
    if (d < 4 * HDIM) gB[d] = bih[d] + bhh[d];
}

__global__ __launch_bounds__(256) void prep_x(const float* __restrict__ x)
{
    size_t idx = (size_t)blockIdx.x * 256 + threadIdx.x;
    __nv_bfloat16 hi, lo; split_bf16(x[idx], hi, lo);
    gX_hi[idx] = hi; gX_lo[idx] = lo;
}

__global__ __launch_bounds__(256) void init_h(
    const float* __restrict__ h0, const float* __restrict__ c0)
{
    int idx = blockIdx.x * 256 + threadIdx.x;
    __nv_bfloat16 hi, lo; split_bf16(h0[idx], hi, lo);
    gH_hi[0][idx] = hi; gH_lo[0][idx] = lo;
    g_c[idx] = c0[idx];
}

// ---------------- zx precompute: zx = x @ W_ih^T (3-term bf16 split) ----------------
// block tile 128(M: 2 timesteps) x 128(N: 4 z-tiles), warp tile 64x32, K=1024/64
__global__ __launch_bounds__(256, 1) void zx_gemm()
{
    extern __shared__ char sm[];
    const uint32_t sb = smem_u32(sm);

    const int tid = threadIdx.x;
    const int w   = tid >> 5;
    const int l   = tid & 31;
    const int wm  = w >> 2;          // 0..1 : rows wm*64..+63
    const int wn  = w & 3;           // 0..3 : cols wn*32..+31
    const int bn  = blockIdx.x;      // 0..31 : z tile-rows bn*128..+127
    const int bm  = blockIdx.y;      // 0..255: x rows bm*128..+127

    const __nv_bfloat16* __restrict__ xh = gX_hi + (size_t)bm * 128 * 1024;
    const __nv_bfloat16* __restrict__ xl = gX_lo + (size_t)bm * 128 * 1024;
    const __nv_bfloat16* __restrict__ wh = gW_hi + (size_t)bn * 128 * KTOT;
    const __nv_bfloat16* __restrict__ wl = gW_lo + (size_t)bn * 128 * KTOT;

    float acc[4][4][4] = {};   // [m16 tile][n8 tile][frag]

    auto load_chunk = [&](int ch, int pb) {
        const uint32_t st = sb + pb * P_STG;
        const int k0 = ch * KB;
        #pragma unroll
        for (int i = 0; i < 4; i++) {            // A hi/lo: 1024 float4 each
            int s = tid + i * 256, r = s >> 3, sg = s & 7;
            uint32_t d = r * P_LDA + sg * 16;
            size_t gofs = (size_t)r * 1024 + k0 + sg * 8;
            cp16(st + d,          xh + gofs);
            cp16(st + P_TILE + d, xl + gofs);
        }
        #pragma unroll
        for (int i = 0; i < 4; i++) {            // B hi/lo: 1024 float4 each
            int s = tid + i * 256, r = s >> 3, sg = s & 7;
            uint32_t d = r * P_LDA + sg * 16;
            size_t gofs = (size_t)r * KTOT + k0 + sg * 8;
            cp16(st + 2 * P_TILE + d, wh + gofs);
            cp16(st + 3 * P_TILE + d, wl + gofs);
        }
        asm volatile("cp.async.commit_group;" ::: "memory");
    };

    const uint32_t rowA = wm * 64 + (l & 7) + ((l >> 3) & 1) * 8;
    const uint32_t acol = (l >> 4) * 16;
    const uint32_t rowB = wn * 32 + (l & 7) + ((l >> 4) & 1) * 8;
    const uint32_t bcol = ((l >> 3) & 1) * 16;

    load_chunk(0, 0);

    for (int ch = 0; ch < 16; ch++) {
        asm volatile("cp.async.wait_group 0;" ::: "memory");
        __syncthreads();
        if (ch + 1 < 16) load_chunk(ch + 1, (ch + 1) & 1);

        const uint32_t st  = sb + (ch & 1) * P_STG;
        const uint32_t aHb = st + rowA * P_LDA + acol;
        const uint32_t aLb = aHb + P_TILE;
        const uint32_t bHb = st + 2 * P_TILE + rowB * P_LDA + bcol;
        const uint32_t bLb = bHb + P_TILE;

        #pragma unroll
        for (int ks = 0; ks < 4; ks++) {
            const uint32_t ko = ks * 32;
            uint32_t ah[4][4], al[4][4], bh[2][4], bl[2][4];
            #pragma unroll
            for (int mt = 0; mt < 4; mt++) {
                ldsm4(ah[mt], aHb + mt * 16 * P_LDA + ko);
                ldsm4(al[mt], aLb + mt * 16 * P_LDA + ko);
            }
            ldsm4(bh[0], bHb + ko);
            ldsm4(bh[1], bHb + 16 * P_LDA + ko);
            ldsm4(bl[0], bLb + ko);
            ldsm4(bl[1], bLb + 16 * P_LDA + ko);
            #pragma unroll
            for (int mt = 0; mt < 4; mt++)
                #pragma unroll
                for (int nt = 0; nt < 4; nt++)
                    mma16816(acc[mt][nt], ah[mt], bh[nt >> 1][(nt & 1) * 2],
                             bh[nt >> 1][(nt & 1) * 2 + 1]);
            #pragma unroll
            for (int mt = 0; mt < 4; mt++)
                #pragma unroll
                for (int nt = 0; nt < 4; nt++)
                    mma16816(acc[mt][nt], ah[mt], bl[nt >> 1][(nt & 1) * 2],
                             bl[nt >> 1][(nt & 1) * 2 + 1]);
            #pragma unroll
            for (int mt = 0; mt < 4; mt++)
                #pragma unroll
                for (int nt = 0; nt < 4; nt++)
                    mma16816(acc[mt][nt], al[mt], bh[nt >> 1][(nt & 1) * 2],
                             bh[nt >> 1][(nt & 1) * 2 + 1]);
        }
    }

    // write zx in step-tile order: [t][blk][r64][c32]
    #pragma unroll
    for (int mt = 0; mt < 4; mt++)
        #pragma unroll
        for (int nt = 0; nt < 4; nt++)
            #pragma unroll
            for (int j = 0; j < 4; j++) {
                int m  = wm * 64 + mt * 16 + (l >> 2) + (j >> 1) * 8;   // 0..127
                int cc = wn * 32 + nt * 8 + (l & 3) * 2 + (j & 1);      // 0..127
                int t  = blockIdx.y * 2 + (m >> 6);
                int r  = m & 63;
                int blk = bn * 4 + (cc >> 5);
                int c   = cc & 31;
                g_zx[(((size_t)t * NBLK + blk) * 64 + r) * 32 + c] = acc[mt][nt][j];
            }
}

// ---------------- per-step kernel (h-part only, K=1024) ----------------
__global__ __launch_bounds__(256, 1) void lstm_step_mma(int t, int rd, int wr)
{
    extern __shared__ char sm[];
    const uint32_t sb = smem_u32(sm);

    const int tid = threadIdx.x;
    const int w   = tid >> 5;
    const int l   = tid & 31;
    const int g   = w >> 1;          // K-group 0..3
    const int wg  = w & 1;           // warp-in-group: rows wg*32..+31
    const int gt  = tid & 63;        // thread-in-group
    const int jh0 = blockIdx.x * HC;

    const __nv_bfloat16* __restrict__ Hhi = gH_hi[rd];
    const __nv_bfloat16* __restrict__ Hlo = gH_lo[rd];
    const __nv_bfloat16* __restrict__ Whi = gW_hi + (size_t)blockIdx.x * ZC * KTOT + IDIM;
    const __nv_bfloat16* __restrict__ Wlo = gW_lo + (size_t)blockIdx.x * ZC * KTOT + IDIM;

    float acc[2][4][4] = {};   // [m16 tile][n8 tile][frag]

    auto load_chunk = [&](int ch, int pb) {
        const uint32_t st = sb + (g * 2 + pb) * STG;
        const int k0 = ch * KB;
        #pragma unroll
        for (int i = 0; i < 8; i++) {            // A hi/lo: 512 float4 each
            int s = gt + i * 64, r = s >> 3, sg = s & 7;
            uint32_t d = r * LDA + sg * 16;
            size_t gofs = (size_t)r * 1024 + k0 + sg * 8;
            cp16(st + d,          Hhi + gofs);
            cp16(st + A_TILE + d, Hlo + gofs);
        }
        #pragma unroll
        for (int i = 0; i < 4; i++) {            // B hi/lo: 256 float4 each
            int s = gt + i * 64, r = s >> 3, sg = s & 7;
            uint32_t d = r * LDA + sg * 16;
            size_t gb = (size_t)r * KTOT + k0 + sg * 8;
            cp16(st + 2 * A_TILE + d,          Whi + gb);
            cp16(st + 2 * A_TILE + B_TILE + d, Wlo + gb);
        }
        asm volatile("cp.async.commit_group;" ::: "memory");
    };

    const uint32_t rowA = wg * 32 + (l & 7) + ((l >> 3) & 1) * 8;
    const uint32_t acol = (l >> 4) * 16;
    const uint32_t rowB = (l & 7) + ((l >> 4) & 1) * 8;
    const uint32_t bcol = ((l >> 3) & 1) * 16;

    load_chunk(g, 0);

    for (int i = 0; i < CPG; i++) {
        const int ch = g + i * NGRP;
        asm volatile("cp.async.wait_group 0;" ::: "memory");
        asm volatile("bar.sync %0, %1;" :: "r"(g + 1), "r"(64) : "memory");
        if (i + 1 < CPG) load_chunk(ch + NGRP, (i + 1) & 1);

        const uint32_t st  = sb + (g * 2 + (i & 1)) * STG;
        const uint32_t aHb = st + rowA * LDA + acol;
        const uint32_t aLb = aHb + A_TILE;
        const uint32_t bHb = st + 2 * A_TILE + rowB * LDA + bcol;
        const uint32_t bLb = bHb + B_TILE;

        #pragma unroll
        for (int ks = 0; ks < 4; ks++) {
            const uint32_t ko = ks * 32;
            uint32_t ah[2][4], al[2][4], bh[2][4], bl[2][4];
            ldsm4(ah[0], aHb + ko);
            ldsm4(ah[1], aHb + 16 * LDA + ko);
            ldsm4(al[0], aLb + ko);
            ldsm4(al[1], aLb + 16 * LDA + ko);
            ldsm4(bh[0], bHb + ko);
            ldsm4(bh[1], bHb + 16 * LDA + ko);
            ldsm4(bl[0], bLb + ko);
            ldsm4(bl[1], bLb + 16 * LDA + ko);
            #pragma unroll
            for (int mt = 0; mt < 2; mt++)
                #pragma unroll
                for (int nt = 0; nt < 4; nt++)
                    mma16816(acc[mt][nt], ah[mt], bh[nt >> 1][(nt & 1) * 2],
                             bh[nt >> 1][(nt & 1) * 2 + 1]);
            #pragma unroll
            for (int mt = 0; mt < 2; mt++)
                #pragma unroll
                for (int nt = 0; nt < 4; nt++)
                    mma16816(acc[mt][nt], ah[mt], bl[nt >> 1][(nt & 1) * 2],
                             bl[nt >> 1][(nt & 1) * 2 + 1]);
            #pragma unroll
            for (int mt = 0; mt < 2; mt++)
                #pragma unroll
                for (int nt = 0; nt < 4; nt++)
                    mma16816(acc[mt][nt], al[mt], bh[nt >> 1][(nt & 1) * 2],
                             bh[nt >> 1][(nt & 1) * 2 + 1]);
        }
    }

    // ---- epilogue: 4 K-partials -> smem -> reduce + zx + gates ----
    __syncthreads();                        // stages dead; reuse for z planes
    float* zs = (float*)sm;                 // [4][64][33]
    const int zb = g * (64 * 33);
    #pragma unroll
    for (int mt = 0; mt < 2; mt++)
        #pragma unroll
        for (int nt = 0; nt < 4; nt++)
            #pragma unroll
            for (int j = 0; j < 4; j++) {
                int r = wg * 32 + mt * 16 + (l >> 2) + (j >> 1) * 8;
                int c = nt * 8 + (l & 3) * 2 + (j & 1);
                zs[zb + r * 33 + c] = acc[mt][nt][j];
            }
    __syncthreads();

    const float* zxp = g_zx + ((size_t)t * NBLK + blockIdx.x) * 64 * 32;
    #pragma unroll
    for (int u = 0; u < 2; u++) {
        int idx = tid * 2 + u;              // 0..511
        int r = idx >> 3, hid = idx & 7;
        int col = jh0 + hid;
        float zi = gB[col]        + zxp[r * 32 + hid];
        float zf = gB[1024 + col] + zxp[r * 32 + 8 + hid];
        float zg = gB[2048 + col] + zxp[r * 32 + 16 + hid];
        float zo = gB[3072 + col] + zxp[r * 32 + 24 + hid];
        #pragma unroll
        for (int q = 0; q < 4; q++) {
            const float* p = zs + q * (64 * 33) + r * 33;
            zi += p[hid]; zf += p[8 + hid]; zg += p[16 + hid]; zo += p[24 + hid];
        }
        float cprev = g_c[r * HDIM + col];
        float ig = 1.0f / (1.0f + expf(-zi));
        float fg = 1.0f / (1.0f + expf(-zf));
        float og = 1.0f / (1.0f + expf(-zo));
        float gg = tanhf(zg);
        float cn = fg * cprev + ig * gg;
        g_c[r * HDIM + col] = cn;
        float hv = og * tanhf(cn);
        g_hf[r * HDIM + col] = hv;
        __nv_bfloat16 hi, lo; split_bf16(hv, hi, lo);
        gH_hi[wr][r * HDIM + col] = hi;
        gH_lo[wr][r * HDIM + col] = lo;
    }
}

// ---------------- final projection ----------------
__global__ __launch_bounds__(128) void out_proj(
    const float* __restrict__ Wout, const float* __restrict__ bout,
    float* __restrict__ y)
{
    int n = blockIdx.y;
    int i = blockIdx.x * 128 + threadIdx.x;
    __shared__ float hs[HDIM];
    for (int k = threadIdx.x; k < HDIM; k += 128) hs[k] = g_hf[n * HDIM + k];
    __syncthreads();
    float acc = bout[i];
    const float* wrow = Wout + (size_t)i * HDIM;
    #pragma unroll 8
    for (int k = 0; k < HDIM; k++) acc += hs[k] * wrow[k];
    y[n * IDIM + i] = acc;
}

__global__ void copy_hc(float* __restrict__ out)
{
    int idx = blockIdx.x * 256 + threadIdx.x;
    out[NB * IDIM + idx]             = g_hf[idx];
    out[NB * IDIM + NB * HDIM + idx] = g_c[idx];
}

// ---------------- launch ----------------
extern "C" void kernel_launch(void* const* d_in, const int* in_sizes, int n_in,
                              void* d_out, int out_size)
{
    const float* x    = (const float*)d_in[0];
    const float* h0   = (const float*)d_in[1];
    const float* c0   = (const float*)d_in[2];
    const float* Wih  = (const float*)d_in[3];
    const float* Whh  = (const float*)d_in[4];
    const float* bih  = (const float*)d_in[5];
    const float* bhh  = (const float*)d_in[6];
    const float* Wout = (const float*)d_in[7];
    const float* bout = (const float*)d_in[8];
    float* out = (float*)d_out;

    cudaFuncSetAttribute(lstm_step_mma,
                         cudaFuncAttributeMaxDynamicSharedMemorySize, SMEM_BYTES);
    cudaFuncSetAttribute(zx_gemm,
                         cudaFuncAttributeMaxDynamicSharedMemorySize, P_SMEM);

    prep_w<<<(NBLK * ZC * KTOT) / 256, 256>>>(Wih, Whh, bih, bhh);
    prep_x<<<(LSEQ * NB * IDIM) / 256, 256>>>(x);
    init_h<<<(NB * HDIM) / 256, 256>>>(h0, c0);

    dim3 pg(32, 256);                    // (N tiles of 128, M tiles of 128)
    zx_gemm<<<pg, 256, P_SMEM>>>();

    for (int t = 0; t < LSEQ; t++)
        lstm_step_mma<<<NBLK, 256, SMEM_BYTES>>>(t, t & 1, (t + 1) & 1);

    dim3 yg(IDIM / 128, NB);
    out_proj<<<yg, 128>>>(Wout, bout, out);
    copy_hc<<<(NB * HDIM) / 256, 256>>>(out);
}

// round 11
// speedup vs baseline: 5.4165x; 1.1286x over previous
#include <cuda_runtime.h>
#include <cuda_bf16.h>
#include <math.h>
#include <stdint.h>

// ---------------- problem dims ----------------
#define LSEQ 512
#define NB   64
#define IDIM 1024
#define HDIM 1024
#define KTOT 2048
#define NBLK 128
#define HC   8
#define ZC   32
#define KB2  32           // per-step A chunk (k)
#define NCH  8            // chunks per group (256 k / 32)
#define NGRP 4

// resident B layout (per group: 32 zc x 256 k x hi/lo)
#define LDB     528                     // 512B data + 16 pad (33x16B, conflict-free)
#define B_SPLIT (32 * LDB)              // 16896
#define B_GRP   (2 * B_SPLIT)           // 33792
#define B_RES   (NGRP * B_GRP)          // 135168
// A stages (per group: 2 stages of 64 rows x 32 k x hi/lo)
#define A_LD    80                      // 64B data + 16 pad (5x16B, conflict-free)
#define A_SPLIT (64 * A_LD)             // 5120
#define A_STAGE (2 * A_SPLIT)           // 10240
#define A_GRP   (2 * A_STAGE)           // 20480
#define A_OFF   B_RES
#define SMEM_P  (B_RES + NGRP * A_GRP)  // 217088

// zx precompute GEMM tiling
#define P_LDA 144
#define P_TILE (128 * P_LDA)
#define P_STG  (4 * P_TILE)
#define P_SMEM (2 * P_STG)              // 147456

// ---------------- device scratch ----------------
__device__ __nv_bfloat16 gW_hi[NBLK * ZC * KTOT];
__device__ __nv_bfloat16 gW_lo[NBLK * ZC * KTOT];
__device__ float         gB[4 * HDIM];
__device__ __nv_bfloat16 gX_hi[LSEQ * NB * IDIM];
__device__ __nv_bfloat16 gX_lo[LSEQ * NB * IDIM];
__device__ __nv_bfloat16 gH_hi[2][NB * HDIM];
__device__ __nv_bfloat16 gH_lo[2][NB * HDIM];
__device__ float         g_c [NB * HDIM];
__device__ float         g_hf[NB * HDIM];
__device__ float         g_zx[(size_t)LSEQ * NBLK * 64 * 32];
__device__ unsigned      g_bar;

// ---------------- helpers ----------------
__device__ __forceinline__ uint32_t smem_u32(const void* p) {
    uint32_t a;
    asm("{ .reg .u64 t; cvta.to.shared.u64 t, %1; cvt.u32.u64 %0, t; }" : "=r"(a) : "l"(p));
    return a;
}
__device__ __forceinline__ void cp16(uint32_t dst, const void* src) {
    asm volatile("cp.async.cg.shared.global [%0], [%1], 16;"
                 :: "r"(dst), "l"(__cvta_generic_to_global(src)));
}
__device__ __forceinline__ void ldsm4(uint32_t* r, uint32_t a) {
    asm volatile("ldmatrix.sync.aligned.m8n8.x4.shared.b16 {%0,%1,%2,%3}, [%4];"
                 : "=r"(r[0]), "=r"(r[1]), "=r"(r[2]), "=r"(r[3]) : "r"(a));
}
__device__ __forceinline__ void mma16816(float* c, const uint32_t* a,
                                         uint32_t b0, uint32_t b1) {
    asm volatile(
        "mma.sync.aligned.m16n8k16.row.col.f32.bf16.bf16.f32 "
        "{%0,%1,%2,%3},{%4,%5,%6,%7},{%8,%9},{%0,%1,%2,%3};"
        : "+f"(c[0]), "+f"(c[1]), "+f"(c[2]), "+f"(c[3])
        : "r"(a[0]), "r"(a[1]), "r"(a[2]), "r"(a[3]), "r"(b0), "r"(b1));
}
__device__ __forceinline__ void split_bf16(float v, __nv_bfloat16& hi, __nv_bfloat16& lo) {
    hi = __float2bfloat16(v);
    lo = __float2bfloat16(v - __bfloat162float(hi));
}

// ---------------- prep kernels ----------------
__global__ void reset_bar() { g_bar = 0; }

__global__ __launch_bounds__(256) void prep_w(
    const float* __restrict__ Wih, const float* __restrict__ Whh,
    const float* __restrict__ bih, const float* __restrict__ bhh)
{
    int d  = blockIdx.x * 256 + threadIdx.x;
    int b  = d >> 16;
    int rr = (d >> 11) & 31;
    int k  = d & 2047;
    int zc = ((rr >> 3) << 10) + b * HC + (rr & 7);
    float w = (k < IDIM) ? Wih[zc * IDIM + k] : Whh[zc * HDIM + (k - IDIM)];
    __nv_bfloat16 hi, lo; split_bf16(w, hi, lo);
    gW_hi[d] = hi; gW_lo[d] = lo;
    if (d < 4 * HDIM) gB[d] = bih[d] + bhh[d];
}

__global__ __launch_bounds__(256) void prep_x(const float* __restrict__ x)
{
    size_t idx = (size_t)blockIdx.x * 256 + threadIdx.x;
    __nv_bfloat16 hi, lo; split_bf16(x[idx], hi, lo);
    gX_hi[idx] = hi; gX_lo[idx] = lo;
}

__global__ __launch_bounds__(256) void init_h(
    const float* __restrict__ h0, const float* __restrict__ c0)
{
    int idx = blockIdx.x * 256 + threadIdx.x;
    __nv_bfloat16 hi, lo; split_bf16(h0[idx], hi, lo);
    gH_hi[0][idx] = hi; gH_lo[0][idx] = lo;
    g_c[idx] = c0[idx];
}

// ---------------- zx precompute: zx = x @ W_ih^T ----------------
__global__ __launch_bounds__(256, 1) void zx_gemm()
{
    extern __shared__ char sm[];
    const uint32_t sb = smem_u32(sm);
    const int tid = threadIdx.x;
    const int w   = tid >> 5;
    const int l   = tid & 31;
    const int wm  = w >> 2;
    const int wn  = w & 3;
    const int bn  = blockIdx.x;
    const int bm  = blockIdx.y;

    const __nv_bfloat16* __restrict__ xh = gX_hi + (size_t)bm * 128 * 1024;
    const __nv_bfloat16* __restrict__ xl = gX_lo + (size_t)bm * 128 * 1024;
    const __nv_bfloat16* __restrict__ wh = gW_hi + (size_t)bn * 128 * KTOT;
    const __nv_bfloat16* __restrict__ wl = gW_lo + (size_t)bn * 128 * KTOT;

    float acc[4][4][4] = {};

    auto load_chunk = [&](int ch, int pb) {
        const uint32_t st = sb + pb * P_STG;
        const int k0 = ch * 64;
        #pragma unroll
        for (int i = 0; i < 4; i++) {
            int s = tid + i * 256, r = s >> 3, sg = s & 7;
            uint32_t d = r * P_LDA + sg * 16;
            size_t gofs = (size_t)r * 1024 + k0 + sg * 8;
            cp16(st + d,          xh + gofs);
            cp16(st + P_TILE + d, xl + gofs);
        }
        #pragma unroll
        for (int i = 0; i < 4; i++) {
            int s = tid + i * 256, r = s >> 3, sg = s & 7;
            uint32_t d = r * P_LDA + sg * 16;
            size_t gofs = (size_t)r * KTOT + k0 + sg * 8;
            cp16(st + 2 * P_TILE + d, wh + gofs);
            cp16(st + 3 * P_TILE + d, wl + gofs);
        }
        asm volatile("cp.async.commit_group;" ::: "memory");
    };

    const uint32_t rowA = wm * 64 + (l & 7) + ((l >> 3) & 1) * 8;
    const uint32_t acol = (l >> 4) * 16;
    const uint32_t rowB = wn * 32 + (l & 7) + ((l >> 4) & 1) * 8;
    const uint32_t bcol = ((l >> 3) & 1) * 16;

    load_chunk(0, 0);

    for (int ch = 0; ch < 16; ch++) {
        asm volatile("cp.async.wait_group 0;" ::: "memory");
        __syncthreads();
        if (ch + 1 < 16) load_chunk(ch + 1, (ch + 1) & 1);

        const uint32_t st  = sb + (ch & 1) * P_STG;
        const uint32_t aHb = st + rowA * P_LDA + acol;
        const uint32_t aLb = aHb + P_TILE;
        const uint32_t bHb = st + 2 * P_TILE + rowB * P_LDA + bcol;
        const uint32_t bLb = bHb + P_TILE;

        #pragma unroll
        for (int ks = 0; ks < 4; ks++) {
            const uint32_t ko = ks * 32;
            uint32_t ah[4][4], al[4][4], bh[2][4], bl[2][4];
            #pragma unroll
            for (int mt = 0; mt < 4; mt++) {
                ldsm4(ah[mt], aHb + mt * 16 * P_LDA + ko);
                ldsm4(al[mt], aLb + mt * 16 * P_LDA + ko);
            }
            ldsm4(bh[0], bHb + ko);
            ldsm4(bh[1], bHb + 16 * P_LDA + ko);
            ldsm4(bl[0], bLb + ko);
            ldsm4(bl[1], bLb + 16 * P_LDA + ko);
            #pragma unroll
            for (int mt = 0; mt < 4; mt++)
                #pragma unroll
                for (int nt = 0; nt < 4; nt++)
                    mma16816(acc[mt][nt], ah[mt], bh[nt >> 1][(nt & 1) * 2],
                             bh[nt >> 1][(nt & 1) * 2 + 1]);
            #pragma unroll
            for (int mt = 0; mt < 4; mt++)
                #pragma unroll
                for (int nt = 0; nt < 4; nt++)
                    mma16816(acc[mt][nt], ah[mt], bl[nt >> 1][(nt & 1) * 2],
                             bl[nt >> 1][(nt & 1) * 2 + 1]);
            #pragma unroll
            for (int mt = 0; mt < 4; mt++)
                #pragma unroll
                for (int nt = 0; nt < 4; nt++)
                    mma16816(acc[mt][nt], al[mt], bh[nt >> 1][(nt & 1) * 2],
                             bh[nt >> 1][(nt & 1) * 2 + 1]);
        }
    }

    #pragma unroll
    for (int mt = 0; mt < 4; mt++)
        #pragma unroll
        for (int nt = 0; nt < 4; nt++)
            #pragma unroll
            for (int j = 0; j < 4; j++) {
                int m  = wm * 64 + mt * 16 + (l >> 2) + (j >> 1) * 8;
                int cc = wn * 32 + nt * 8 + (l & 3) * 2 + (j & 1);
                int t  = blockIdx.y * 2 + (m >> 6);
                int r  = m & 63;
                int blk = bn * 4 + (cc >> 5);
                int c   = cc & 31;
                g_zx[(((size_t)t * NBLK + blk) * 64 + r) * 32 + c] = acc[mt][nt][j];
            }
}

// ---------------- persistent recurrent kernel ----------------
__global__ __launch_bounds__(256, 1) void lstm_persist()
{
    extern __shared__ char sm[];
    const uint32_t sb = smem_u32(sm);
    const int tid = threadIdx.x;
    const int w   = tid >> 5, l = tid & 31;
    const int g   = w >> 1,  wg = w & 1;
    const int gt  = tid & 63;
    const int blk = blockIdx.x;
    const int jh0 = blk * HC;

    const __nv_bfloat16* __restrict__ Whi = gW_hi + (size_t)blk * ZC * KTOT + IDIM;
    const __nv_bfloat16* __restrict__ Wlo = gW_lo + (size_t)blk * ZC * KTOT + IDIM;

    // ---- one-time: load resident B (this group's K quarter) ----
    const uint32_t bgrp = sb + g * B_GRP;
    {
        const int kb = g * 256;
        #pragma unroll
        for (int j = 0; j < 16; j++) {
            int idx = gt + j * 64;
            int r = idx >> 5, sg = idx & 31;
            uint32_t d = r * LDB + sg * 16;
            cp16(bgrp + d,           Whi + (size_t)r * KTOT + kb + sg * 8);
            cp16(bgrp + B_SPLIT + d, Wlo + (size_t)r * KTOT + kb + sg * 8);
        }
        asm volatile("cp.async.commit_group;" ::: "memory");
    }

    const uint32_t agrp = sb + A_OFF + g * A_GRP;
    const uint32_t rowA = wg * 32 + (l & 7) + ((l >> 3) & 1) * 8;
    const uint32_t acol = (l >> 4) * 16;
    const uint32_t rowB = (l & 7) + ((l >> 4) & 1) * 8;
    const uint32_t bcol = ((l >> 3) & 1) * 16;

    // ---- per-thread epilogue state (fixed ownership across steps) ----
    int   erow[2], ecol[2];
    float bia[2][4], creg[2];
    #pragma unroll
    for (int u = 0; u < 2; u++) {
        int idx = tid * 2 + u;
        erow[u] = idx >> 3;
        ecol[u] = jh0 + (idx & 7);
        bia[u][0] = gB[ecol[u]];
        bia[u][1] = gB[1024 + ecol[u]];
        bia[u][2] = gB[2048 + ecol[u]];
        bia[u][3] = gB[3072 + ecol[u]];
        creg[u] = g_c[erow[u] * HDIM + ecol[u]];
    }

    #pragma unroll 1
    for (int s = 0; s < LSEQ; s++) {
        const __nv_bfloat16* __restrict__ Hhi = gH_hi[s & 1];
        const __nv_bfloat16* __restrict__ Hlo = gH_lo[s & 1];

        // prefetch zx for this step into registers
        const float* zxp = g_zx + ((size_t)s * NBLK + blk) * 64 * 32;
        float zxr[2][4];
        #pragma unroll
        for (int u = 0; u < 2; u++) {
            int base = erow[u] * 32 + (ecol[u] - jh0);
            zxr[u][0] = zxp[base];
            zxr[u][1] = zxp[base + 8];
            zxr[u][2] = zxp[base + 16];
            zxr[u][3] = zxp[base + 24];
        }

        // A chunk = 64 rows x 32 k = 4 x 16B segments per row per split
        auto load_A = [&](int i) {
            const uint32_t st = agrp + (i & 1) * A_STAGE;
            const int k0 = g * 256 + i * KB2;
            #pragma unroll
            for (int j = 0; j < 4; j++) {               // 256 segs / 64 thr = 4
                int e = gt + j * 64;
                int r = e >> 2, sg = e & 3;             // r in [0,63], sg in [0,3]
                uint32_t d = r * A_LD + sg * 16;
                cp16(st + d,           Hhi + (size_t)r * 1024 + k0 + sg * 8);
                cp16(st + A_SPLIT + d, Hlo + (size_t)r * 1024 + k0 + sg * 8);
            }
            asm volatile("cp.async.commit_group;" ::: "memory");
        };

        float acc[2][4][4] = {};
        load_A(0);

        for (int i = 0; i < NCH; i++) {
            if (i + 1 < NCH) {
                load_A(i + 1);
                asm volatile("cp.async.wait_group 1;" ::: "memory");
            } else {
                asm volatile("cp.async.wait_group 0;" ::: "memory");
            }
            asm volatile("bar.sync %0, %1;" :: "r"(g + 1), "r"(64) : "memory");

            const uint32_t st  = agrp + (i & 1) * A_STAGE;
            const uint32_t aHb = st + rowA * A_LD + acol;
            const uint32_t aLb = aHb + A_SPLIT;
            const uint32_t bHb = bgrp + i * 64 + rowB * LDB + bcol;
            const uint32_t bLb = bHb + B_SPLIT;

            #pragma unroll
            for (int ks = 0; ks < 2; ks++) {
                const uint32_t ko = ks * 32;
                uint32_t ah[2][4], al[2][4], bh[2][4], bl[2][4];
                ldsm4(ah[0], aHb + ko);
                ldsm4(ah[1], aHb + 16 * A_LD + ko);
                ldsm4(al[0], aLb + ko);
                ldsm4(al[1], aLb + 16 * A_LD + ko);
                ldsm4(bh[0], bHb + ko);
                ldsm4(bh[1], bHb + 16 * LDB + ko);
                ldsm4(bl[0], bLb + ko);
                ldsm4(bl[1], bLb + 16 * LDB + ko);
                #pragma unroll
                for (int mt = 0; mt < 2; mt++)
                    #pragma unroll
                    for (int nt = 0; nt < 4; nt++)
                        mma16816(acc[mt][nt], ah[mt], bh[nt >> 1][(nt & 1) * 2],
                                 bh[nt >> 1][(nt & 1) * 2 + 1]);
                #pragma unroll
                for (int mt = 0; mt < 2; mt++)
                    #pragma unroll
                    for (int nt = 0; nt < 4; nt++)
                        mma16816(acc[mt][nt], ah[mt], bl[nt >> 1][(nt & 1) * 2],
                                 bl[nt >> 1][(nt & 1) * 2 + 1]);
                #pragma unroll
                for (int mt = 0; mt < 2; mt++)
                    #pragma unroll
                    for (int nt = 0; nt < 4; nt++)
                        mma16816(acc[mt][nt], al[mt], bh[nt >> 1][(nt & 1) * 2],
                                 bh[nt >> 1][(nt & 1) * 2 + 1]);
            }
            asm volatile("bar.sync %0, %1;" :: "r"(g + 1), "r"(64) : "memory");
        }

        // ---- epilogue: partials -> smem (overlay A stages) -> gates ----
        __syncthreads();
        float* zs = (float*)(sm + A_OFF);          // [4][64][33]
        const int zb = g * (64 * 33);
        #pragma unroll
        for (int mt = 0; mt < 2; mt++)
            #pragma unroll
            for (int nt = 0; nt < 4; nt++)
                #pragma unroll
                for (int j = 0; j < 4; j++) {
                    int r = wg * 32 + mt * 16 + (l >> 2) + (j >> 1) * 8;
                    int c = nt * 8 + (l & 3) * 2 + (j & 1);
                    zs[zb + r * 33 + c] = acc[mt][nt][j];
                }
        __syncthreads();

        const int wrb = (s + 1) & 1;
        #pragma unroll
        for (int u = 0; u < 2; u++) {
            int r = erow[u], col = ecol[u], hid = col - jh0;
            float zi = bia[u][0] + zxr[u][0];
            float zf = bia[u][1] + zxr[u][1];
            float zg = bia[u][2] + zxr[u][2];
            float zo = bia[u][3] + zxr[u][3];
            #pragma unroll
            for (int q = 0; q < 4; q++) {
                const float* p = zs + q * (64 * 33) + r * 33;
                zi += p[hid]; zf += p[8 + hid]; zg += p[16 + hid]; zo += p[24 + hid];
            }
            float ig = 1.0f / (1.0f + expf(-zi));
            float fg = 1.0f / (1.0f + expf(-zf));
            float og = 1.0f / (1.0f + expf(-zo));
            float gg = tanhf(zg);
            creg[u] = fg * creg[u] + ig * gg;
            float hv = og * tanhf(creg[u]);
            __nv_bfloat16 hi, lo; split_bf16(hv, hi, lo);
            gH_hi[wrb][r * HDIM + col] = hi;
            gH_lo[wrb][r * HDIM + col] = lo;
            if (s == LSEQ - 1) {
                g_hf[r * HDIM + col] = hv;
                g_c [r * HDIM + col] = creg[u];
            }
        }

        // ---- grid barrier (release h writes, acquire for next step) ----
        if (s + 1 < LSEQ) {
            __threadfence();
            __syncthreads();
            if (tid == 0) {
                atomicAdd(&g_bar, 1u);
                unsigned target = (unsigned)(s + 1) * (unsigned)NBLK;
                while (*(volatile unsigned*)&g_bar < target) __nanosleep(64);
                __threadfence();
            }
            __syncthreads();
        }
    }
}

// ---------------- final projection ----------------
__global__ __launch_bounds__(128) void out_proj(
    const float* __restrict__ Wout, const float* __restrict__ bout,
    float* __restrict__ y)
{
    int n = blockIdx.y;
    int i = blockIdx.x * 128 + threadIdx.x;
    __shared__ float hs[HDIM];
    for (int k = threadIdx.x; k < HDIM; k += 128) hs[k] = g_hf[n * HDIM + k];
    __syncthreads();
    float acc = bout[i];
    const float* wrow = Wout + (size_t)i * HDIM;
    #pragma unroll 8
    for (int k = 0; k < HDIM; k++) acc += hs[k] * wrow[k];
    y[n * IDIM + i] = acc;
}

__global__ void copy_hc(float* __restrict__ out)
{
    int idx = blockIdx.x * 256 + threadIdx.x;
    out[NB * IDIM + idx]             = g_hf[idx];
    out[NB * IDIM + NB * HDIM + idx] = g_c[idx];
}

// ---------------- launch ----------------
extern "C" void kernel_launch(void* const* d_in, const int* in_sizes, int n_in,
                              void* d_out, int out_size)
{
    const float* x    = (const float*)d_in[0];
    const float* h0   = (const float*)d_in[1];
    const float* c0   = (const float*)d_in[2];
    const float* Wih  = (const float*)d_in[3];
    const float* Whh  = (const float*)d_in[4];
    const float* bih  = (const float*)d_in[5];
    const float* bhh  = (const float*)d_in[6];
    const float* Wout = (const float*)d_in[7];
    const float* bout = (const float*)d_in[8];
    float* out = (float*)d_out;

    cudaFuncSetAttribute(lstm_persist,
                         cudaFuncAttributeMaxDynamicSharedMemorySize, SMEM_P);
    cudaFuncSetAttribute(zx_gemm,
                         cudaFuncAttributeMaxDynamicSharedMemorySize, P_SMEM);

    reset_bar<<<1, 1>>>();
    prep_w<<<(NBLK * ZC * KTOT) / 256, 256>>>(Wih, Whh, bih, bhh);
    prep_x<<<(LSEQ * NB * IDIM) / 256, 256>>>(x);
    init_h<<<(NB * HDIM) / 256, 256>>>(h0, c0);

    dim3 pg(32, 256);
    zx_gemm<<<pg, 256, P_SMEM>>>();

    lstm_persist<<<NBLK, 256, SMEM_P>>>();

    dim3 yg(IDIM / 128, NB);
    out_proj<<<yg, 128>>>(Wout, bout, out);
    copy_hc<<<(NB * HDIM) / 256, 256>>>(out);
}

// round 13
// speedup vs baseline: 6.6048x; 1.2194x over previous
#include <cuda_runtime.h>
#include <cuda_bf16.h>
#include <cuda_fp16.h>
#include <math.h>
#include <stdint.h>

// ---------------- problem dims ----------------
#define LSEQ 512
#define NB   64
#define IDIM 1024
#define HDIM 1024
#define KTOT 2048
#define NBLK 128
#define HC   8
#define ZC   32
#define KB2  32           // per-step A chunk (k)
#define NCH  8            // chunks per group (256 k / 32)
#define NGRP 4

// resident B layout (per group: 32 zc x 256 k x hi/lo, fp16)
#define LDB     528                     // 512B data + 16 pad
#define B_SPLIT (32 * LDB)              // 16896
#define B_GRP   (2 * B_SPLIT)           // 33792
#define B_RES   (NGRP * B_GRP)          // 135168
// A stages (per group: 4 stages of 64 rows x 32 k, single fp16)
#define A_LD    80                      // 64B data + 16 pad
#define A_SPLIT (64 * A_LD)             // 5120
#define A_GRP   (4 * A_SPLIT)           // 20480 (4 stages)
#define A_OFF   B_RES
#define SMEM_P  (B_RES + NGRP * A_GRP)  // 217088

// zx precompute GEMM tiling (bf16 3-term)
#define P_LDA 144
#define P_TILE (128 * P_LDA)
#define P_STG  (4 * P_TILE)
#define P_SMEM (2 * P_STG)              // 147456

// ---------------- device scratch ----------------
__device__ __nv_bfloat16 gW_hi[NBLK * ZC * KTOT];   // bf16 (zx path, x half)
__device__ __nv_bfloat16 gW_lo[NBLK * ZC * KTOT];
__device__ __half        gV_hi[NBLK * ZC * HDIM];   // fp16 W_hh block-major
__device__ __half        gV_lo[NBLK * ZC * HDIM];
__device__ float         gB[4 * HDIM];
__device__ __nv_bfloat16 gX_hi[LSEQ * NB * IDIM];
__device__ __nv_bfloat16 gX_lo[LSEQ * NB * IDIM];
__device__ __half        gH[2][NB * HDIM];          // h ping-pong, single fp16
__device__ float         g_c [NB * HDIM];
__device__ float         g_hf[NB * HDIM];
__device__ float         g_zx[(size_t)LSEQ * NBLK * 64 * 32];
__device__ unsigned      g_bar;

// ---------------- helpers ----------------
__device__ __forceinline__ uint32_t smem_u32(const void* p) {
    uint32_t a;
    asm("{ .reg .u64 t; cvta.to.shared.u64 t, %1; cvt.u32.u64 %0, t; }" : "=r"(a) : "l"(p));
    return a;
}
__device__ __forceinline__ void cp16(uint32_t dst, const void* src) {
    asm volatile("cp.async.cg.shared.global [%0], [%1], 16;"
                 :: "r"(dst), "l"(__cvta_generic_to_global(src)));
}
__device__ __forceinline__ void ldsm4(uint32_t* r, uint32_t a) {
    asm volatile("ldmatrix.sync.aligned.m8n8.x4.shared.b16 {%0,%1,%2,%3}, [%4];"
                 : "=r"(r[0]), "=r"(r[1]), "=r"(r[2]), "=r"(r[3]) : "r"(a));
}
__device__ __forceinline__ void mma_bf16(float* c, const uint32_t* a,
                                         uint32_t b0, uint32_t b1) {
    asm volatile(
        "mma.sync.aligned.m16n8k16.row.col.f32.bf16.bf16.f32 "
        "{%0,%1,%2,%3},{%4,%5,%6,%7},{%8,%9},{%0,%1,%2,%3};"
        : "+f"(c[0]), "+f"(c[1]), "+f"(c[2]), "+f"(c[3])
        : "r"(a[0]), "r"(a[1]), "r"(a[2]), "r"(a[3]), "r"(b0), "r"(b1));
}
__device__ __forceinline__ void mma_f16(float* c, const uint32_t* a,
                                        uint32_t b0, uint32_t b1) {
    asm volatile(
        "mma.sync.aligned.m16n8k16.row.col.f32.f16.f16.f32 "
        "{%0,%1,%2,%3},{%4,%5,%6,%7},{%8,%9},{%0,%1,%2,%3};"
        : "+f"(c[0]), "+f"(c[1]), "+f"(c[2]), "+f"(c[3])
        : "r"(a[0]), "r"(a[1]), "r"(a[2]), "r"(a[3]), "r"(b0), "r"(b1));
}
__device__ __forceinline__ void split_bf16(float v, __nv_bfloat16& hi, __nv_bfloat16& lo) {
    hi = __float2bfloat16(v);
    lo = __float2bfloat16(v - __bfloat162float(hi));
}
__device__ __forceinline__ void split_f16(float v, __half& hi, __half& lo) {
    hi = __float2half(v);
    lo = __float2half(v - __half2float(hi));
}

// ---------------- prep kernels ----------------
__global__ void reset_bar() { g_bar = 0; }

__global__ __launch_bounds__(256) void prep_w(
    const float* __restrict__ Wih, const float* __restrict__ Whh,
    const float* __restrict__ bih, const float* __restrict__ bhh)
{
    int d  = blockIdx.x * 256 + threadIdx.x;
    int b  = d >> 16;
    int rr = (d >> 11) & 31;
    int k  = d & 2047;
    int zc = ((rr >> 3) << 10) + b * HC + (rr & 7);
    float w = (k < IDIM) ? Wih[zc * IDIM + k] : Whh[zc * HDIM + (k - IDIM)];
    __nv_bfloat16 hi, lo; split_bf16(w, hi, lo);
    gW_hi[d] = hi; gW_lo[d] = lo;
    if (k >= IDIM) {
        __half h2, l2; split_f16(w, h2, l2);
        int vi = (b * ZC + rr) * HDIM + (k - IDIM);
        gV_hi[vi] = h2; gV_lo[vi] = l2;
    }
    if (d < 4 * HDIM) gB[d] = bih[d] + bhh[d];
}

__global__ __launch_bounds__(256) void prep_x(const float* __restrict__ x)
{
    size_t idx = (size_t)blockIdx.x * 256 + threadIdx.x;
    __nv_bfloat16 hi, lo; split_bf16(x[idx], hi, lo);
    gX_hi[idx] = hi; gX_lo[idx] = lo;
}

__global__ __launch_bounds__(256) void init_h(
    const float* __restrict__ h0, const float* __restrict__ c0)
{
    int idx = blockIdx.x * 256 + threadIdx.x;
    gH[0][idx] = __float2half(h0[idx]);
    g_c[idx] = c0[idx];
}

// ---------------- zx precompute: zx = x @ W_ih^T (bf16 3-term) ----------------
__global__ __launch_bounds__(256, 1) void zx_gemm()
{
    extern __shared__ char sm[];
    const uint32_t sb = smem_u32(sm);
    const int tid = threadIdx.x;
    const int w   = tid >> 5;
    const int l   = tid & 31;
    const int wm  = w >> 2;
    const int wn  = w & 3;
    const int bn  = blockIdx.x;
    const int bm  = blockIdx.y;

    const __nv_bfloat16* __restrict__ xh = gX_hi + (size_t)bm * 128 * 1024;
    const __nv_bfloat16* __restrict__ xl = gX_lo + (size_t)bm * 128 * 1024;
    const __nv_bfloat16* __restrict__ wh = gW_hi + (size_t)bn * 128 * KTOT;
    const __nv_bfloat16* __restrict__ wl = gW_lo + (size_t)bn * 128 * KTOT;

    float acc[4][4][4] = {};

    auto load_chunk = [&](int ch, int pb) {
        const uint32_t st = sb + pb * P_STG;
        const int k0 = ch * 64;
        #pragma unroll
        for (int i = 0; i < 4; i++) {
            int s = tid + i * 256, r = s >> 3, sg = s & 7;
            uint32_t d = r * P_LDA + sg * 16;
            size_t gofs = (size_t)r * 1024 + k0 + sg * 8;
            cp16(st + d,          xh + gofs);
            cp16(st + P_TILE + d, xl + gofs);
        }
        #pragma unroll
        for (int i = 0; i < 4; i++) {
            int s = tid + i * 256, r = s >> 3, sg = s & 7;
            uint32_t d = r * P_LDA + sg * 16;
            size_t gofs = (size_t)r * KTOT + k0 + sg * 8;
            cp16(st + 2 * P_TILE + d, wh + gofs);
            cp16(st + 3 * P_TILE + d, wl + gofs);
        }
        asm volatile("cp.async.commit_group;" ::: "memory");
    };

    const uint32_t rowA = wm * 64 + (l & 7) + ((l >> 3) & 1) * 8;
    const uint32_t acol = (l >> 4) * 16;
    const uint32_t rowB = wn * 32 + (l & 7) + ((l >> 4) & 1) * 8;
    const uint32_t bcol = ((l >> 3) & 1) * 16;

    load_chunk(0, 0);

    for (int ch = 0; ch < 16; ch++) {
        asm volatile("cp.async.wait_group 0;" ::: "memory");
        __syncthreads();
        if (ch + 1 < 16) load_chunk(ch + 1, (ch + 1) & 1);

        const uint32_t st  = sb + (ch & 1) * P_STG;
        const uint32_t aHb = st + rowA * P_LDA + acol;
        const uint32_t aLb = aHb + P_TILE;
        const uint32_t bHb = st + 2 * P_TILE + rowB * P_LDA + bcol;
        const uint32_t bLb = bHb + P_TILE;

        #pragma unroll
        for (int ks = 0; ks < 4; ks++) {
            const uint32_t ko = ks * 32;
            uint32_t ah[4][4], al[4][4], bh[2][4], bl[2][4];
            #pragma unroll
            for (int mt = 0; mt < 4; mt++) {
                ldsm4(ah[mt], aHb + mt * 16 * P_LDA + ko);
                ldsm4(al[mt], aLb + mt * 16 * P_LDA + ko);
            }
            ldsm4(bh[0], bHb + ko);
            ldsm4(bh[1], bHb + 16 * P_LDA + ko);
            ldsm4(bl[0], bLb + ko);
            ldsm4(bl[1], bLb + 16 * P_LDA + ko);
            #pragma unroll
            for (int mt = 0; mt < 4; mt++)
                #pragma unroll
                for (int nt = 0; nt < 4; nt++)
                    mma_bf16(acc[mt][nt], ah[mt], bh[nt >> 1][(nt & 1) * 2],
                             bh[nt >> 1][(nt & 1) * 2 + 1]);
            #pragma unroll
            for (int mt = 0; mt < 4; mt++)
                #pragma unroll
                for (int nt = 0; nt < 4; nt++)
                    mma_bf16(acc[mt][nt], ah[mt], bl[nt >> 1][(nt & 1) * 2],
                             bl[nt >> 1][(nt & 1) * 2 + 1]);
            #pragma unroll
            for (int mt = 0; mt < 4; mt++)
                #pragma unroll
                for (int nt = 0; nt < 4; nt++)
                    mma_bf16(acc[mt][nt], al[mt], bh[nt >> 1][(nt & 1) * 2],
                             bh[nt >> 1][(nt & 1) * 2 + 1]);
        }
    }

    #pragma unroll
    for (int mt = 0; mt < 4; mt++)
        #pragma unroll
        for (int nt = 0; nt < 4; nt++)
            #pragma unroll
            for (int j = 0; j < 4; j++) {
                int m  = wm * 64 + mt * 16 + (l >> 2) + (j >> 1) * 8;
                int cc = wn * 32 + nt * 8 + (l & 3) * 2 + (j & 1);
                int t  = blockIdx.y * 2 + (m >> 6);
                int r  = m & 63;
                int blk = bn * 4 + (cc >> 5);
                int c   = cc & 31;
                g_zx[(((size_t)t * NBLK + blk) * 64 + r) * 32 + c] = acc[mt][nt][j];
            }
}

// ---------------- persistent recurrent kernel (fp16 2-term) ----------------
__global__ __launch_bounds__(256, 1) void lstm_persist()
{
    extern __shared__ char sm[];
    const uint32_t sb = smem_u32(sm);
    const int tid = threadIdx.x;
    const int w   = tid >> 5, l = tid & 31;
    const int g   = w >> 1,  wg = w & 1;
    const int gt  = tid & 63;
    const int blk = blockIdx.x;
    const int jh0 = blk * HC;

    const __half* __restrict__ Vhi = gV_hi + (size_t)blk * ZC * HDIM;
    const __half* __restrict__ Vlo = gV_lo + (size_t)blk * ZC * HDIM;

    // ---- one-time: load resident B (this group's K quarter, fp16 hi/lo) ----
    const uint32_t bgrp = sb + g * B_GRP;
    {
        const int kb = g * 256;
        #pragma unroll
        for (int j = 0; j < 16; j++) {
            int idx = gt + j * 64;
            int r = idx >> 5, sg = idx & 31;
            uint32_t d = r * LDB + sg * 16;
            cp16(bgrp + d,           Vhi + (size_t)r * HDIM + kb + sg * 8);
            cp16(bgrp + B_SPLIT + d, Vlo + (size_t)r * HDIM + kb + sg * 8);
        }
        asm volatile("cp.async.commit_group;" ::: "memory");
    }

    const uint32_t agrp = sb + A_OFF + g * A_GRP;
    const uint32_t rowA = wg * 32 + (l & 7) + ((l >> 3) & 1) * 8;
    const uint32_t acol = (l >> 4) * 16;
    const uint32_t rowB = (l & 7) + ((l >> 4) & 1) * 8;
    const uint32_t bcol = ((l >> 3) & 1) * 16;

    // ---- per-thread epilogue state ----
    int   erow[2], ecol[2];
    float bia[2][4], creg[2];
    #pragma unroll
    for (int u = 0; u < 2; u++) {
        int idx = tid * 2 + u;
        erow[u] = idx >> 3;
        ecol[u] = jh0 + (idx & 7);
        bia[u][0] = gB[ecol[u]];
        bia[u][1] = gB[1024 + ecol[u]];
        bia[u][2] = gB[2048 + ecol[u]];
        bia[u][3] = gB[3072 + ecol[u]];
        creg[u] = g_c[erow[u] * HDIM + ecol[u]];
    }

    #pragma unroll 1
    for (int s = 0; s < LSEQ; s++) {
        const __half* __restrict__ Hp = gH[s & 1];

        // zx prefetch into registers
        const float* zxp = g_zx + ((size_t)s * NBLK + blk) * 64 * 32;
        float zxr[2][4];
        #pragma unroll
        for (int u = 0; u < 2; u++) {
            int base = erow[u] * 32 + (ecol[u] - jh0);
            zxr[u][0] = zxp[base];
            zxr[u][1] = zxp[base + 8];
            zxr[u][2] = zxp[base + 16];
            zxr[u][3] = zxp[base + 24];
        }

        // A chunk = 64 rows x 32 k fp16 (single split): 4 segs/row
        auto load_A = [&](int i) {
            const uint32_t st = agrp + (i & 3) * A_SPLIT;
            const int k0 = g * 256 + i * KB2;
            #pragma unroll
            for (int j = 0; j < 4; j++) {               // 256 segs / 64 thr
                int e = gt + j * 64;
                int r = e >> 2, sg = e & 3;
                cp16(st + r * A_LD + sg * 16, Hp + (size_t)r * HDIM + k0 + sg * 8);
            }
            asm volatile("cp.async.commit_group;" ::: "memory");
        };

        float acc[2][4][4] = {};
        load_A(0); load_A(1); load_A(2);

        for (int i = 0; i < NCH; i++) {
            // wait for MY copies of chunk i, THEN group barrier so everyone's
            // copies are visible (and everyone is done computing chunk i-1).
            if (i < NCH - 2)       asm volatile("cp.async.wait_group 2;" ::: "memory");
            else if (i == NCH - 2) asm volatile("cp.async.wait_group 1;" ::: "memory");
            else                   asm volatile("cp.async.wait_group 0;" ::: "memory");
            asm volatile("bar.sync %0, %1;" :: "r"(g + 1), "r"(64) : "memory");
            if (i + 3 < NCH) load_A(i + 3);

            const uint32_t st  = agrp + (i & 3) * A_SPLIT;
            const uint32_t aHb = st + rowA * A_LD + acol;
            const uint32_t bHb = bgrp + i * 64 + rowB * LDB + bcol;
            const uint32_t bLb = bHb + B_SPLIT;

            #pragma unroll
            for (int ks = 0; ks < 2; ks++) {
                const uint32_t ko = ks * 32;
                uint32_t ah[2][4], bh[2][4], bl[2][4];
                ldsm4(ah[0], aHb + ko);
                ldsm4(ah[1], aHb + 16 * A_LD + ko);
                ldsm4(bh[0], bHb + ko);
                ldsm4(bh[1], bHb + 16 * LDB + ko);
                ldsm4(bl[0], bLb + ko);
                ldsm4(bl[1], bLb + 16 * LDB + ko);
                #pragma unroll
                for (int mt = 0; mt < 2; mt++)
                    #pragma unroll
                    for (int nt = 0; nt < 4; nt++)
                        mma_f16(acc[mt][nt], ah[mt], bh[nt >> 1][(nt & 1) * 2],
                                bh[nt >> 1][(nt & 1) * 2 + 1]);
                #pragma unroll
                for (int mt = 0; mt < 2; mt++)
                    #pragma unroll
                    for (int nt = 0; nt < 4; nt++)
                        mma_f16(acc[mt][nt], ah[mt], bl[nt >> 1][(nt & 1) * 2],
                                bl[nt >> 1][(nt & 1) * 2 + 1]);
            }
        }

        // ---- epilogue: partials -> smem (overlay A stages) -> gates ----
        __syncthreads();
        float* zs = (float*)(sm + A_OFF);          // [4][64][33]
        const int zb = g * (64 * 33);
        #pragma unroll
        for (int mt = 0; mt < 2; mt++)
            #pragma unroll
            for (int nt = 0; nt < 4; nt++)
                #pragma unroll
                for (int j = 0; j < 4; j++) {
                    int r = wg * 32 + mt * 16 + (l >> 2) + (j >> 1) * 8;
                    int c = nt * 8 + (l & 3) * 2 + (j & 1);
                    zs[zb + r * 33 + c] = acc[mt][nt][j];
                }
        __syncthreads();

        const int wrb = (s + 1) & 1;
        #pragma unroll
        for (int u = 0; u < 2; u++) {
            int r = erow[u], col = ecol[u], hid = col - jh0;
            float zi = bia[u][0] + zxr[u][0];
            float zf = bia[u][1] + zxr[u][1];
            float zg = bia[u][2] + zxr[u][2];
            float zo = bia[u][3] + zxr[u][3];
            #pragma unroll
            for (int q = 0; q < 4; q++) {
                const float* p = zs + q * (64 * 33) + r * 33;
                zi += p[hid]; zf += p[8 + hid]; zg += p[16 + hid]; zo += p[24 + hid];
            }
            float ig = 1.0f / (1.0f + expf(-zi));
            float fg = 1.0f / (1.0f + expf(-zf));
            float og = 1.0f / (1.0f + expf(-zo));
            float gg = tanhf(zg);
            creg[u] = fg * creg[u] + ig * gg;
            float hv = og * tanhf(creg[u]);
            gH[wrb][r * HDIM + col] = __float2half(hv);
            if (s == LSEQ - 1) {
                g_hf[r * HDIM + col] = hv;
                g_c [r * HDIM + col] = creg[u];
            }
        }

        // ---- grid barrier ----
        if (s + 1 < LSEQ) {
            __threadfence();
            __syncthreads();
            if (tid == 0) {
                atomicAdd(&g_bar, 1u);
                unsigned target = (unsigned)(s + 1) * (unsigned)NBLK;
                while (*(volatile unsigned*)&g_bar < target) __nanosleep(64);
                __threadfence();
            }
            __syncthreads();
        }
    }
}

// ---------------- final projection ----------------
__global__ __launch_bounds__(128) void out_proj(
    const float* __restrict__ Wout, const float* __restrict__ bout,
    float* __restrict__ y)
{
    int n = blockIdx.y;
    int i = blockIdx.x * 128 + threadIdx.x;
    __shared__ float hs[HDIM];
    for (int k = threadIdx.x; k < HDIM; k += 128) hs[k] = g_hf[n * HDIM + k];
    __syncthreads();
    float acc = bout[i];
    const float* wrow = Wout + (size_t)i * HDIM;
    #pragma unroll 8
    for (int k = 0; k < HDIM; k++) acc += hs[k] * wrow[k];
    y[n * IDIM + i] = acc;
}

__global__ void copy_hc(float* __restrict__ out)
{
    int idx = blockIdx.x * 256 + threadIdx.x;
    out[NB * IDIM + idx]             = g_hf[idx];
    out[NB * IDIM + NB * HDIM + idx] = g_c[idx];
}

// ---------------- launch ----------------
extern "C" void kernel_launch(void* const* d_in, const int* in_sizes, int n_in,
                              void* d_out, int out_size)
{
    const float* x    = (const float*)d_in[0];
    const float* h0   = (const float*)d_in[1];
    const float* c0   = (const float*)d_in[2];
    const float* Wih  = (const float*)d_in[3];
    const float* Whh  = (const float*)d_in[4];
    const float* bih  = (const float*)d_in[5];
    const float* bhh  = (const float*)d_in[6];
    const float* Wout = (const float*)d_in[7];
    const float* bout = (const float*)d_in[8];
    float* out = (float*)d_out;

    cudaFuncSetAttribute(lstm_persist,
                         cudaFuncAttributeMaxDynamicSharedMemorySize, SMEM_P);
    cudaFuncSetAttribute(zx_gemm,
                         cudaFuncAttributeMaxDynamicSharedMemorySize, P_SMEM);

    reset_bar<<<1, 1>>>();
    prep_w<<<(NBLK * ZC * KTOT) / 256, 256>>>(Wih, Whh, bih, bhh);
    prep_x<<<(LSEQ * NB * IDIM) / 256, 256>>>(x);
    init_h<<<(NB * HDIM) / 256, 256>>>(h0, c0);

    dim3 pg(32, 256);
    zx_gemm<<<pg, 256, P_SMEM>>>();

    lstm_persist<<<NBLK, 256, SMEM_P>>>();

    dim3 yg(IDIM / 128, NB);
    out_proj<<<yg, 128>>>(Wout, bout, out);
    copy_hc<<<(NB * HDIM) / 256, 256>>>(out);
}

// round 16
// speedup vs baseline: 9.2384x; 1.3988x over previous
#include <cuda_runtime.h>
#include <cuda_fp16.h>
#include <math.h>
#include <stdint.h>

// ---------------- problem dims ----------------
#define LSEQ 512
#define NB   64
#define IDIM 1024
#define HDIM 1024
#define KTOT 2048
#define NBLK 128
#define HC   8
#define ZC   32
#define KB2  32           // per-step A chunk (k)
#define NCH  8            // chunks per group (256 k / 32)
#define NGRP 4
#define NSTG 6            // A pipeline depth

// resident B (per group: 32 zc x 256 k, single fp16)
#define LDB     528                     // 512B data + 16 pad
#define B_SPLIT (32 * LDB)              // 16896
#define B_RES   (NGRP * B_SPLIT)        // 67584
// A stages (per group: NSTG stages of 64 rows x 32 k fp16)
#define A_LD    80                      // 64B data + 16 pad
#define A_SPLIT (64 * A_LD)             // 5120
#define A_GRP   (NSTG * A_SPLIT)        // 30720
#define A_OFF   B_RES
#define SMEM_P  (B_RES + NGRP * A_GRP)  // 190464

// zx precompute GEMM tiling (single-term fp16)
#define P_LDA 144
#define P_TILE (128 * P_LDA)            // 18432
#define P_STG  (2 * P_TILE)             // A + B = 36864
#define P_SMEM (2 * P_STG)              // 73728

// ---------------- device scratch ----------------
__device__ __half gWx[NBLK * ZC * IDIM];    // fp16 W_ih block-major (zx path)
__device__ __half gV [NBLK * ZC * HDIM];    // fp16 W_hh block-major (recurrent)
__device__ float  gB[4 * HDIM];
__device__ __half gX[(size_t)LSEQ * NB * IDIM];   // fp16 x
__device__ __half gH[2][NB * HDIM];         // h ping-pong fp16
__device__ float  g_c [NB * HDIM];
__device__ float  g_hf[NB * HDIM];
__device__ float  g_zx[(size_t)LSEQ * NBLK * 64 * 32];
__device__ unsigned g_bar;

// ---------------- helpers ----------------
__device__ __forceinline__ uint32_t smem_u32(const void* p) {
    uint32_t a;
    asm("{ .reg .u64 t; cvta.to.shared.u64 t, %1; cvt.u32.u64 %0, t; }" : "=r"(a) : "l"(p));
    return a;
}
__device__ __forceinline__ void cp16(uint32_t dst, const void* src) {
    asm volatile("cp.async.cg.shared.global [%0], [%1], 16;"
                 :: "r"(dst), "l"(__cvta_generic_to_global(src)));
}
__device__ __forceinline__ void ldsm4(uint32_t* r, uint32_t a) {
    asm volatile("ldmatrix.sync.aligned.m8n8.x4.shared.b16 {%0,%1,%2,%3}, [%4];"
                 : "=r"(r[0]), "=r"(r[1]), "=r"(r[2]), "=r"(r[3]) : "r"(a));
}
__device__ __forceinline__ void mma_f16(float* c, const uint32_t* a,
                                        uint32_t b0, uint32_t b1) {
    asm volatile(
        "mma.sync.aligned.m16n8k16.row.col.f32.f16.f16.f32 "
        "{%0,%1,%2,%3},{%4,%5,%6,%7},{%8,%9},{%0,%1,%2,%3};"
        : "+f"(c[0]), "+f"(c[1]), "+f"(c[2]), "+f"(c[3])
        : "r"(a[0]), "r"(a[1]), "r"(a[2]), "r"(a[3]), "r"(b0), "r"(b1));
}

// ---------------- prep kernels ----------------
__global__ void reset_bar() { g_bar = 0; }

__global__ __launch_bounds__(256) void prep_w(
    const float* __restrict__ Wih, const float* __restrict__ Whh,
    const float* __restrict__ bih, const float* __restrict__ bhh)
{
    int d  = blockIdx.x * 256 + threadIdx.x;   // 0 .. 8388607
    int b  = d >> 16;
    int rr = (d >> 11) & 31;
    int k  = d & 2047;
    int zc = ((rr >> 3) << 10) + b * HC + (rr & 7);
    if (k < IDIM) {
        gWx[(b * ZC + rr) * IDIM + k] = __float2half(Wih[zc * IDIM + k]);
    } else {
        gV[(b * ZC + rr) * HDIM + (k - IDIM)] = __float2half(Whh[zc * HDIM + (k - IDIM)]);
    }
    if (d < 4 * HDIM) gB[d] = bih[d] + bhh[d];
}

__global__ __launch_bounds__(256) void prep_x(const float* __restrict__ x)
{
    size_t idx = (size_t)blockIdx.x * 256 + threadIdx.x;
    gX[idx] = __float2half(x[idx]);
}

__global__ __launch_bounds__(256) void init_h(
    const float* __restrict__ h0, const float* __restrict__ c0)
{
    int idx = blockIdx.x * 256 + threadIdx.x;
    gH[0][idx] = __float2half(h0[idx]);
    g_c[idx] = c0[idx];
}

// ---------------- zx precompute: zx = x @ W_ih^T (single-term fp16) ----------------
__global__ __launch_bounds__(256, 1) void zx_gemm()
{
    extern __shared__ char sm[];
    const uint32_t sb = smem_u32(sm);
    const int tid = threadIdx.x;
    const int w   = tid >> 5;
    const int l   = tid & 31;
    const int wm  = w >> 2;          // 0..1: rows wm*64..+63
    const int wn  = w & 3;           // 0..3: cols wn*32..+31
    const int bn  = blockIdx.x;      // 0..31
    const int bm  = blockIdx.y;      // 0..255

    const __half* __restrict__ xp = gX  + (size_t)bm * 128 * IDIM;
    const __half* __restrict__ wp = gWx + (size_t)bn * 128 * IDIM;

    float acc[4][4][4] = {};

    auto load_chunk = [&](int ch, int pb) {
        const uint32_t st = sb + pb * P_STG;
        const int k0 = ch * 64;
        #pragma unroll
        for (int i = 0; i < 4; i++) {            // A: 1024 segs
            int s = tid + i * 256, r = s >> 3, sg = s & 7;
            cp16(st + r * P_LDA + sg * 16, xp + (size_t)r * IDIM + k0 + sg * 8);
        }
        #pragma unroll
        for (int i = 0; i < 4; i++) {            // B: 1024 segs
            int s = tid + i * 256, r = s >> 3, sg = s & 7;
            cp16(st + P_TILE + r * P_LDA + sg * 16, wp + (size_t)r * IDIM + k0 + sg * 8);
        }
        asm volatile("cp.async.commit_group;" ::: "memory");
    };

    const uint32_t rowA = wm * 64 + (l & 7) + ((l >> 3) & 1) * 8;
    const uint32_t acol = (l >> 4) * 16;
    const uint32_t rowB = wn * 32 + (l & 7) + ((l >> 4) & 1) * 8;
    const uint32_t bcol = ((l >> 3) & 1) * 16;

    load_chunk(0, 0);

    for (int ch = 0; ch < 16; ch++) {
        asm volatile("cp.async.wait_group 0;" ::: "memory");
        __syncthreads();
        if (ch + 1 < 16) load_chunk(ch + 1, (ch + 1) & 1);

        const uint32_t st  = sb + (ch & 1) * P_STG;
        const uint32_t aHb = st + rowA * P_LDA + acol;
        const uint32_t bHb = st + P_TILE + rowB * P_LDA + bcol;

        #pragma unroll
        for (int ks = 0; ks < 4; ks++) {
            const uint32_t ko = ks * 32;
            uint32_t ah[4][4], bh[2][4];
            #pragma unroll
            for (int mt = 0; mt < 4; mt++)
                ldsm4(ah[mt], aHb + mt * 16 * P_LDA + ko);
            ldsm4(bh[0], bHb + ko);
            ldsm4(bh[1], bHb + 16 * P_LDA + ko);
            #pragma unroll
            for (int mt = 0; mt < 4; mt++)
                #pragma unroll
                for (int nt = 0; nt < 4; nt++)
                    mma_f16(acc[mt][nt], ah[mt], bh[nt >> 1][(nt & 1) * 2],
                            bh[nt >> 1][(nt & 1) * 2 + 1]);
        }
    }

    // write zx in step-tile order: [t][blk][r64][c32]
    #pragma unroll
    for (int mt = 0; mt < 4; mt++)
        #pragma unroll
        for (int nt = 0; nt < 4; nt++)
            #pragma unroll
            for (int j = 0; j < 4; j++) {
                int m  = wm * 64 + mt * 16 + (l >> 2) + (j >> 1) * 8;
                int cc = wn * 32 + nt * 8 + (l & 3) * 2 + (j & 1);
                int t  = blockIdx.y * 2 + (m >> 6);
                int r  = m & 63;
                int blk = bn * 4 + (cc >> 5);
                int c   = cc & 31;
                g_zx[(((size_t)t * NBLK + blk) * 64 + r) * 32 + c] = acc[mt][nt][j];
            }
}

// ---------------- persistent recurrent kernel (single-term fp16) ----------------
__global__ __launch_bounds__(256, 1) void lstm_persist()
{
    extern __shared__ char sm[];
    const uint32_t sb = smem_u32(sm);
    const int tid = threadIdx.x;
    const int w   = tid >> 5, l = tid & 31;
    const int g   = w >> 1,  wg = w & 1;
    const int gt  = tid & 63;
    const int blk = blockIdx.x;
    const int jh0 = blk * HC;

    const __half* __restrict__ Vp = gV + (size_t)blk * ZC * HDIM;

    // ---- one-time: resident B (this group's K quarter, single fp16) ----
    const uint32_t bgrp = sb + g * B_SPLIT;
    {
        const int kb = g * 256;
        #pragma unroll
        for (int j = 0; j < 16; j++) {
            int idx = gt + j * 64;
            int r = idx >> 5, sg = idx & 31;
            cp16(bgrp + r * LDB + sg * 16, Vp + (size_t)r * HDIM + kb + sg * 8);
        }
        asm volatile("cp.async.commit_group;" ::: "memory");
    }

    const uint32_t agrp = sb + A_OFF + g * A_GRP;
    const uint32_t rowA = wg * 32 + (l & 7) + ((l >> 3) & 1) * 8;
    const uint32_t acol = (l >> 4) * 16;
    const uint32_t rowB = (l & 7) + ((l >> 4) & 1) * 8;
    const uint32_t bcol = ((l >> 3) & 1) * 16;

    // ---- per-thread epilogue state ----
    int   erow[2], ecol[2];
    float bia[2][4], creg[2];
    #pragma unroll
    for (int u = 0; u < 2; u++) {
        int idx = tid * 2 + u;
        erow[u] = idx >> 3;
        ecol[u] = jh0 + (idx & 7);
        bia[u][0] = gB[ecol[u]];
        bia[u][1] = gB[1024 + ecol[u]];
        bia[u][2] = gB[2048 + ecol[u]];
        bia[u][3] = gB[3072 + ecol[u]];
        creg[u] = g_c[erow[u] * HDIM + ecol[u]];
    }

    #pragma unroll 1
    for (int s = 0; s < LSEQ; s++) {
        const __half* __restrict__ Hp = gH[s & 1];

        // zx prefetch into registers
        const float* zxp = g_zx + ((size_t)s * NBLK + blk) * 64 * 32;
        float zxr[2][4];
        #pragma unroll
        for (int u = 0; u < 2; u++) {
            int base = erow[u] * 32 + (ecol[u] - jh0);
            zxr[u][0] = zxp[base];
            zxr[u][1] = zxp[base + 8];
            zxr[u][2] = zxp[base + 16];
            zxr[u][3] = zxp[base + 24];
        }

        auto load_A = [&](int i) {
            const uint32_t st = agrp + (i % NSTG) * A_SPLIT;
            const int k0 = g * 256 + i * KB2;
            #pragma unroll
            for (int j = 0; j < 4; j++) {
                int e = gt + j * 64;
                int r = e >> 2, sg = e & 3;
                cp16(st + r * A_LD + sg * 16, Hp + (size_t)r * HDIM + k0 + sg * 8);
            }
            asm volatile("cp.async.commit_group;" ::: "memory");
        };

        float acc[2][4][4] = {};
        load_A(0); load_A(1); load_A(2); load_A(3); load_A(4);

        for (int i = 0; i < NCH; i++) {
            // wait for chunk i (outstanding = issued - (i+1)), then group barrier
            if (i <= 3)      asm volatile("cp.async.wait_group 4;" ::: "memory");
            else if (i == 4) asm volatile("cp.async.wait_group 3;" ::: "memory");
            else if (i == 5) asm volatile("cp.async.wait_group 2;" ::: "memory");
            else if (i == 6) asm volatile("cp.async.wait_group 1;" ::: "memory");
            else             asm volatile("cp.async.wait_group 0;" ::: "memory");
            asm volatile("bar.sync %0, %1;" :: "r"(g + 1), "r"(64) : "memory");
            if (i + 5 < NCH) load_A(i + 5);

            const uint32_t st  = agrp + (i % NSTG) * A_SPLIT;
            const uint32_t aHb = st + rowA * A_LD + acol;
            const uint32_t bHb = bgrp + i * 64 + rowB * LDB + bcol;

            #pragma unroll
            for (int ks = 0; ks < 2; ks++) {
                const uint32_t ko = ks * 32;
                uint32_t ah[2][4], bh[2][4];
                ldsm4(ah[0], aHb + ko);
                ldsm4(ah[1], aHb + 16 * A_LD + ko);
                ldsm4(bh[0], bHb + ko);
                ldsm4(bh[1], bHb + 16 * LDB + ko);
                #pragma unroll
                for (int mt = 0; mt < 2; mt++)
                    #pragma unroll
                    for (int nt = 0; nt < 4; nt++)
                        mma_f16(acc[mt][nt], ah[mt], bh[nt >> 1][(nt & 1) * 2],
                                bh[nt >> 1][(nt & 1) * 2 + 1]);
            }
        }

        // ---- epilogue: partials -> smem (overlay A stages) -> gates ----
        __syncthreads();
        float* zs = (float*)(sm + A_OFF);          // [4][64][33]
        const int zb = g * (64 * 33);
        #pragma unroll
        for (int mt = 0; mt < 2; mt++)
            #pragma unroll
            for (int nt = 0; nt < 4; nt++)
                #pragma unroll
                for (int j = 0; j < 4; j++) {
                    int r = wg * 32 + mt * 16 + (l >> 2) + (j >> 1) * 8;
                    int c = nt * 8 + (l & 3) * 2 + (j & 1);
                    zs[zb + r * 33 + c] = acc[mt][nt][j];
                }
        __syncthreads();

        const int wrb = (s + 1) & 1;
        #pragma unroll
        for (int u = 0; u < 2; u++) {
            int r = erow[u], col = ecol[u], hid = col - jh0;
            float zi = bia[u][0] + zxr[u][0];
            float zf = bia[u][1] + zxr[u][1];
            float zg = bia[u][2] + zxr[u][2];
            float zo = bia[u][3] + zxr[u][3];
            #pragma unroll
            for (int q = 0; q < 4; q++) {
                const float* p = zs + q * (64 * 33) + r * 33;
                zi += p[hid]; zf += p[8 + hid]; zg += p[16 + hid]; zo += p[24 + hid];
            }
            float ig = 1.0f / (1.0f + expf(-zi));
            float fg = 1.0f / (1.0f + expf(-zf));
            float og = 1.0f / (1.0f + expf(-zo));
            float gg = tanhf(zg);
            creg[u] = fg * creg[u] + ig * gg;
            float hv = og * tanhf(creg[u]);
            gH[wrb][r * HDIM + col] = __float2half(hv);
            if (s == LSEQ - 1) {
                g_hf[r * HDIM + col] = hv;
                g_c [r * HDIM + col] = creg[u];
            }
        }

        // ---- grid barrier: release-add + acquire-poll (no full MEMBAR) ----
        if (s + 1 < LSEQ) {
            __syncthreads();   // all threads' h writes ordered before release
            if (tid == 0) {
                asm volatile("red.release.gpu.add.u32 [%0], 1;"
                             :: "l"(&g_bar) : "memory");
                unsigned target = (unsigned)(s + 1) * (unsigned)NBLK;
                unsigned v;
                while (true) {
                    asm volatile("ld.acquire.gpu.u32 %0, [%1];"
                                 : "=r"(v) : "l"(&g_bar) : "memory");
                    if (v >= target) break;
                    __nanosleep(64);
                }
            }
            __syncthreads();
        }
    }
}

// ---------------- final projection ----------------
__global__ __launch_bounds__(128) void out_proj(
    const float* __restrict__ Wout, const float* __restrict__ bout,
    float* __restrict__ y)
{
    int n = blockIdx.y;
    int i = blockIdx.x * 128 + threadIdx.x;
    __shared__ float hs[HDIM];
    for (int k = threadIdx.x; k < HDIM; k += 128) hs[k] = g_hf[n * HDIM + k];
    __syncthreads();
    float acc = bout[i];
    const float* wrow = Wout + (size_t)i * HDIM;
    #pragma unroll 8
    for (int k = 0; k < HDIM; k++) acc += hs[k] * wrow[k];
    y[n * IDIM + i] = acc;
}

__global__ void copy_hc(float* __restrict__ out)
{
    int idx = blockIdx.x * 256 + threadIdx.x;
    out[NB * IDIM + idx]             = g_hf[idx];
    out[NB * IDIM + NB * HDIM + idx] = g_c[idx];
}

// ---------------- launch ----------------
extern "C" void kernel_launch(void* const* d_in, const int* in_sizes, int n_in,
                              void* d_out, int out_size)
{
    const float* x    = (const float*)d_in[0];
    const float* h0   = (const float*)d_in[1];
    const float* c0   = (const float*)d_in[2];
    const float* Wih  = (const float*)d_in[3];
    const float* Whh  = (const float*)d_in[4];
    const float* bih  = (const float*)d_in[5];
    const float* bhh  = (const float*)d_in[6];
    const float* Wout = (const float*)d_in[7];
    const float* bout = (const float*)d_in[8];
    float* out = (float*)d_out;

    cudaFuncSetAttribute(lstm_persist,
                         cudaFuncAttributeMaxDynamicSharedMemorySize, SMEM_P);
    cudaFuncSetAttribute(zx_gemm,
                         cudaFuncAttributeMaxDynamicSharedMemorySize, P_SMEM);

    reset_bar<<<1, 1>>>();
    prep_w<<<(NBLK * ZC * KTOT) / 256, 256>>>(Wih, Whh, bih, bhh);
    prep_x<<<(int)(((size_t)LSEQ * NB * IDIM) / 256), 256>>>(x);
    init_h<<<(NB * HDIM) / 256, 256>>>(h0, c0);

    dim3 pg(32, 256);
    zx_gemm<<<pg, 256, P_SMEM>>>();

    lstm_persist<<<NBLK, 256, SMEM_P>>>();

    dim3 yg(IDIM / 128, NB);
    out_proj<<<yg, 128>>>(Wout, bout, out);
    copy_hc<<<(NB * HDIM) / 256, 256>>>(out);
}